// round 1
// baseline (speedup 1.0000x reference)
#include <cuda_runtime.h>
#include <math.h>
#include <stdint.h>

// Problem constants
#define BB 2
#define TT 2048
#define DIM 2048
#define NH 16
#define NKV 4
#define NREP 4
#define ROPE_D 64
#define NOPE_D 128
#define V_D 128
#define QK_D 192
#define KV_RANK 512
#define Q_RANK 1536
#define MROWS (BB*TT)   // 4096

// ------------------------- scratch (static device memory) -------------------
__device__ float g_kv_c  [MROWS * KV_RANK];          // 4096x512
__device__ float g_q_c   [MROWS * Q_RANK];           // 4096x1536
__device__ float g_k_nope[MROWS * (NKV*NOPE_D)];     // 4096x512
__device__ float g_k_rope[MROWS * (NKV*ROPE_D)];     // 4096x256
__device__ float g_v     [MROWS * (NKV*V_D)];        // 4096x512
__device__ float g_q_nope[MROWS * (NH*NOPE_D)];      // 4096x2048
__device__ float g_q_rope[MROWS * (NH*ROPE_D)];      // 4096x1024
__device__ float g_qcat  [BB*NH  * TT * QK_D];       // [B,H,T,192]
__device__ float g_kcat  [BB*NKV * TT * QK_D];       // [B,HKV,T,192]
__device__ float g_attn  [MROWS * (NH*V_D)];         // 4096x2048

// ------------------------- generic SGEMM 128x128x8 --------------------------
// C[M,N] = A[M,K] @ B[K,N], row-major. Requires M%128==0, N%128==0, K%8==0.
__global__ __launch_bounds__(256) void sgemm128(
    const float* __restrict__ A, const float* __restrict__ B,
    float* __restrict__ C, int M, int N, int K)
{
    __shared__ float As[8][128];
    __shared__ float Bs[8][128];

    const int tid = threadIdx.x;
    const int bx = blockIdx.x, by = blockIdx.y;

    const int arow = tid >> 1;           // 0..127
    const int acol = (tid & 1) * 4;      // 0 or 4
    const int brow = tid >> 5;           // 0..7
    const int bcol = (tid & 31) * 4;     // 0..124

    const int tx = tid & 15;             // col group
    const int ty = tid >> 4;             // row group

    const float* Ab = A + (size_t)by * 128 * K;
    const float* Bb = B + bx * 128;
    float*       Cb = C + (size_t)by * 128 * N + bx * 128;

    float acc[8][8];
    #pragma unroll
    for (int i = 0; i < 8; i++)
        #pragma unroll
        for (int j = 0; j < 8; j++) acc[i][j] = 0.f;

    for (int k0 = 0; k0 < K; k0 += 8) {
        float4 a = *(const float4*)(Ab + (size_t)arow * K + k0 + acol);
        As[acol + 0][arow] = a.x;
        As[acol + 1][arow] = a.y;
        As[acol + 2][arow] = a.z;
        As[acol + 3][arow] = a.w;
        float4 b = *(const float4*)(Bb + (size_t)(k0 + brow) * N + bcol);
        *(float4*)&Bs[brow][bcol] = b;
        __syncthreads();

        #pragma unroll
        for (int kk = 0; kk < 8; kk++) {
            float4 a0 = *(float4*)&As[kk][ty * 8];
            float4 a1 = *(float4*)&As[kk][ty * 8 + 4];
            float4 b0 = *(float4*)&Bs[kk][tx * 8];
            float4 b1 = *(float4*)&Bs[kk][tx * 8 + 4];
            float ar[8] = {a0.x,a0.y,a0.z,a0.w,a1.x,a1.y,a1.z,a1.w};
            float br[8] = {b0.x,b0.y,b0.z,b0.w,b1.x,b1.y,b1.z,b1.w};
            #pragma unroll
            for (int i = 0; i < 8; i++)
                #pragma unroll
                for (int j = 0; j < 8; j++)
                    acc[i][j] += ar[i] * br[j];
        }
        __syncthreads();
    }

    #pragma unroll
    for (int i = 0; i < 8; i++) {
        #pragma unroll
        for (int j = 0; j < 8; j += 4) {
            float4 v = make_float4(acc[i][j], acc[i][j+1], acc[i][j+2], acc[i][j+3]);
            *(float4*)(Cb + (size_t)(ty * 8 + i) * N + tx * 8 + j) = v;
        }
    }
}

// ------------------------- RoPE + assembly ----------------------------------
__device__ __forceinline__ float rope_val(const float* base, size_t rowoff,
                                          int dr, int t)
{
    int j = dr & 31;
    float theta = 1.0f / powf(10000.0f, (float)j * (1.0f / 32.0f));
    float ang = (float)t * theta;
    float c = cosf(ang), s = sinf(ang);
    float x0  = base[rowoff + dr];
    float rot = (dr < 32) ? -base[rowoff + dr + 32] : base[rowoff + dr - 32];
    return x0 * c + rot * s;
}

// q_cat[b][h][t][d]: d<128 -> q_nope, d>=128 -> rope(q_rope)
__global__ void assemble_q(const float* __restrict__ qn,
                           const float* __restrict__ qr,
                           float* __restrict__ qcat)
{
    size_t idx = (size_t)blockIdx.x * blockDim.x + threadIdx.x;
    const size_t total = (size_t)BB * NH * TT * QK_D;
    if (idx >= total) return;
    int d = (int)(idx % QK_D);
    size_t rem = idx / QK_D;
    int t = (int)(rem % TT); rem /= TT;
    int h = (int)(rem % NH);
    int b = (int)(rem / NH);
    size_t row = (size_t)b * TT + t;
    float val;
    if (d < NOPE_D) {
        val = qn[row * (NH * NOPE_D) + h * NOPE_D + d];
    } else {
        val = rope_val(qr, row * (NH * ROPE_D) + h * ROPE_D, d - NOPE_D, t);
    }
    qcat[idx] = val;
}

__global__ void assemble_k(const float* __restrict__ kn,
                           const float* __restrict__ kr,
                           float* __restrict__ kcat)
{
    size_t idx = (size_t)blockIdx.x * blockDim.x + threadIdx.x;
    const size_t total = (size_t)BB * NKV * TT * QK_D;
    if (idx >= total) return;
    int d = (int)(idx % QK_D);
    size_t rem = idx / QK_D;
    int t = (int)(rem % TT); rem /= TT;
    int h = (int)(rem % NKV);
    int b = (int)(rem / NKV);
    size_t row = (size_t)b * TT + t;
    float val;
    if (d < NOPE_D) {
        val = kn[row * (NKV * NOPE_D) + h * NOPE_D + d];
    } else {
        val = rope_val(kr, row * (NKV * ROPE_D) + h * ROPE_D, d - NOPE_D, t);
    }
    kcat[idx] = val;
}

// ------------------------- flash attention ----------------------------------
// Grid: (T/64, B*H). Block: 256 threads. Causal, online softmax.
// q: [B,H,T,192], k: [B,HKV,T,192], v: [B,T,HKV*128] (raw projection output)
// out: [B,T,H*128]
#define LDQK 68
#define LDV 132
#define LDS_S 68
#define ATTN_SMEM_FLOATS (192*LDQK*2 + 64*LDV + 64*LDS_S + 192)

__global__ __launch_bounds__(256) void flash_attn(
    const float* __restrict__ q, const float* __restrict__ k,
    const float* __restrict__ v, float* __restrict__ out)
{
    extern __shared__ float sm[];
    float* Qt   = sm;                    // [192][68] transposed
    float* Kt   = Qt + 192 * LDQK;       // [192][68]
    float* Vs   = Kt + 192 * LDQK;       // [64][132]
    float* Ss   = Vs + 64 * LDV;         // [64][68]
    float* mrow = Ss + 64 * LDS_S;       // [64]
    float* lrow = mrow + 64;
    float* arow = lrow + 64;

    const int qtile = blockIdx.x;
    const int head  = blockIdx.y;        // b*NH + h
    const int b = head / NH, h = head % NH;
    const int hkv = h / NREP;
    const int tid = threadIdx.x;
    const int tx = tid & 15, ty = tid >> 4;

    const float scale = rsqrtf((float)QK_D);

    const float* qbase = q + ((size_t)head * TT + (size_t)qtile * 64) * QK_D;
    const float* kbase = k + ((size_t)(b * NKV + hkv) * TT) * QK_D;
    const float* vbase = v + (size_t)b * TT * (NKV * V_D) + hkv * V_D;

    for (int i = tid; i < 64 * QK_D; i += 256) {
        int r = i / QK_D, d = i % QK_D;
        Qt[d * LDQK + r] = qbase[(size_t)r * QK_D + d];
    }
    if (tid < 64) { mrow[tid] = -1e30f; lrow[tid] = 0.f; }

    float acc[4][8];
    #pragma unroll
    for (int i = 0; i < 4; i++)
        #pragma unroll
        for (int j = 0; j < 8; j++) acc[i][j] = 0.f;

    __syncthreads();

    const int qrow0 = qtile * 64;
    const int qr = ty * 4, kc = tx * 4;
    const int orow = ty * 4, ocol = tx * 8;

    for (int jt = 0; jt <= qtile; jt++) {
        const int krow0 = jt * 64;
        for (int i = tid; i < 64 * QK_D; i += 256) {
            int r = i / QK_D, d = i % QK_D;
            Kt[d * LDQK + r] = kbase[(size_t)(krow0 + r) * QK_D + d];
        }
        for (int i = tid; i < 64 * V_D; i += 256) {
            int r = i / V_D, d = i % V_D;
            Vs[r * LDV + d] = vbase[(size_t)(krow0 + r) * (NKV * V_D) + d];
        }
        __syncthreads();

        // S = Q @ K^T (each thread 4x4)
        float s[4][4];
        #pragma unroll
        for (int i = 0; i < 4; i++)
            #pragma unroll
            for (int j = 0; j < 4; j++) s[i][j] = 0.f;

        for (int d = 0; d < QK_D; d++) {
            float a0 = Qt[d*LDQK + qr + 0];
            float a1 = Qt[d*LDQK + qr + 1];
            float a2 = Qt[d*LDQK + qr + 2];
            float a3 = Qt[d*LDQK + qr + 3];
            float b0 = Kt[d*LDQK + kc + 0];
            float b1 = Kt[d*LDQK + kc + 1];
            float b2 = Kt[d*LDQK + kc + 2];
            float b3 = Kt[d*LDQK + kc + 3];
            s[0][0]+=a0*b0; s[0][1]+=a0*b1; s[0][2]+=a0*b2; s[0][3]+=a0*b3;
            s[1][0]+=a1*b0; s[1][1]+=a1*b1; s[1][2]+=a1*b2; s[1][3]+=a1*b3;
            s[2][0]+=a2*b0; s[2][1]+=a2*b1; s[2][2]+=a2*b2; s[2][3]+=a2*b3;
            s[3][0]+=a3*b0; s[3][1]+=a3*b1; s[3][2]+=a3*b2; s[3][3]+=a3*b3;
        }

        const bool diag = (jt == qtile);
        #pragma unroll
        for (int i = 0; i < 4; i++)
            #pragma unroll
            for (int j = 0; j < 4; j++) {
                float val = s[i][j] * scale;
                if (diag && (krow0 + kc + j > qrow0 + qr + i)) val = -1e30f;
                Ss[(qr + i) * LDS_S + kc + j] = val;
            }
        __syncthreads();

        // online softmax per row
        if (tid < 64) {
            float mo = mrow[tid];
            float mn = mo;
            for (int c = 0; c < 64; c++) mn = fmaxf(mn, Ss[tid * LDS_S + c]);
            float al = __expf(mo - mn);
            float ls = 0.f;
            for (int c = 0; c < 64; c++) {
                float p = __expf(Ss[tid * LDS_S + c] - mn);
                Ss[tid * LDS_S + c] = p;
                ls += p;
            }
            mrow[tid] = mn;
            lrow[tid] = lrow[tid] * al + ls;
            arow[tid] = al;
        }
        __syncthreads();

        // O = O*alpha + P @ V (each thread 4 rows x 8 cols)
        #pragma unroll
        for (int i = 0; i < 4; i++) {
            float al = arow[orow + i];
            #pragma unroll
            for (int j = 0; j < 8; j++) acc[i][j] *= al;
        }
        for (int kk = 0; kk < 64; kk++) {
            float4 v0 = *(float4*)&Vs[kk * LDV + ocol];
            float4 v1 = *(float4*)&Vs[kk * LDV + ocol + 4];
            float vv[8] = {v0.x,v0.y,v0.z,v0.w,v1.x,v1.y,v1.z,v1.w};
            #pragma unroll
            for (int i = 0; i < 4; i++) {
                float p = Ss[(orow + i) * LDS_S + kk];
                #pragma unroll
                for (int j = 0; j < 8; j++) acc[i][j] += p * vv[j];
            }
        }
        __syncthreads();
    }

    // normalize + write out [B,T,H*128]
    #pragma unroll
    for (int i = 0; i < 4; i++) {
        float inv = 1.0f / lrow[orow + i];
        size_t row = (size_t)b * TT + qrow0 + orow + i;
        #pragma unroll
        for (int j = 0; j < 8; j += 4) {
            float4 o = make_float4(acc[i][j]*inv, acc[i][j+1]*inv,
                                   acc[i][j+2]*inv, acc[i][j+3]*inv);
            *(float4*)(out + row * (NH * V_D) + h * V_D + ocol + j) = o;
        }
    }
}

// ------------------------- launch -------------------------------------------
static inline dim3 gemm_grid(int M, int N) { return dim3(N / 128, M / 128); }

extern "C" void kernel_launch(void* const* d_in, const int* in_sizes, int n_in,
                              void* d_out, int out_size)
{
    const float* x         = (const float*)d_in[0];
    const float* W_kv_down = (const float*)d_in[1];
    const float* W_k_nope  = (const float*)d_in[2];
    const float* W_k_rope  = (const float*)d_in[3];
    const float* W_v       = (const float*)d_in[4];
    const float* W_q_down  = (const float*)d_in[5];
    const float* W_q_nope  = (const float*)d_in[6];
    const float* W_q_rope  = (const float*)d_in[7];
    const float* W_o       = (const float*)d_in[8];
    float* out = (float*)d_out;

    float *kv_c, *q_c, *k_nope, *k_rope, *v, *q_nope, *q_rope, *qcat, *kcat, *attn;
    cudaGetSymbolAddress((void**)&kv_c,   g_kv_c);
    cudaGetSymbolAddress((void**)&q_c,    g_q_c);
    cudaGetSymbolAddress((void**)&k_nope, g_k_nope);
    cudaGetSymbolAddress((void**)&k_rope, g_k_rope);
    cudaGetSymbolAddress((void**)&v,      g_v);
    cudaGetSymbolAddress((void**)&q_nope, g_q_nope);
    cudaGetSymbolAddress((void**)&q_rope, g_q_rope);
    cudaGetSymbolAddress((void**)&qcat,   g_qcat);
    cudaGetSymbolAddress((void**)&kcat,   g_kcat);
    cudaGetSymbolAddress((void**)&attn,   g_attn);

    const size_t attn_smem = ATTN_SMEM_FLOATS * sizeof(float);
    cudaFuncSetAttribute(flash_attn, cudaFuncAttributeMaxDynamicSharedMemorySize,
                         (int)attn_smem);

    // down projections
    sgemm128<<<gemm_grid(MROWS, KV_RANK), 256>>>(x, W_kv_down, kv_c, MROWS, KV_RANK, DIM);
    sgemm128<<<gemm_grid(MROWS, Q_RANK),  256>>>(x, W_q_down,  q_c,  MROWS, Q_RANK,  DIM);

    // up projections
    sgemm128<<<gemm_grid(MROWS, NKV*NOPE_D), 256>>>(kv_c, W_k_nope, k_nope, MROWS, NKV*NOPE_D, KV_RANK);
    sgemm128<<<gemm_grid(MROWS, NKV*ROPE_D), 256>>>(kv_c, W_k_rope, k_rope, MROWS, NKV*ROPE_D, KV_RANK);
    sgemm128<<<gemm_grid(MROWS, NKV*V_D),    256>>>(kv_c, W_v,      v,      MROWS, NKV*V_D,    KV_RANK);
    sgemm128<<<gemm_grid(MROWS, NH*NOPE_D),  256>>>(q_c,  W_q_nope, q_nope, MROWS, NH*NOPE_D,  Q_RANK);
    sgemm128<<<gemm_grid(MROWS, NH*ROPE_D),  256>>>(q_c,  W_q_rope, q_rope, MROWS, NH*ROPE_D,  Q_RANK);

    // RoPE + layout assembly
    {
        size_t nq = (size_t)BB * NH * TT * QK_D;
        assemble_q<<<(unsigned)((nq + 255) / 256), 256>>>(q_nope, q_rope, qcat);
        size_t nk = (size_t)BB * NKV * TT * QK_D;
        assemble_k<<<(unsigned)((nk + 255) / 256), 256>>>(k_nope, k_rope, kcat);
    }

    // attention
    flash_attn<<<dim3(TT / 64, BB * NH), 256, attn_smem>>>(qcat, kcat, v, attn);

    // output projection
    sgemm128<<<gemm_grid(MROWS, DIM), 256>>>(attn, W_o, out, MROWS, DIM, NH*V_D);
}

// round 2
// speedup vs baseline: 1.6012x; 1.6012x over previous
#include <cuda_runtime.h>
#include <math.h>
#include <stdint.h>

// Problem constants
#define BB 2
#define TT 2048
#define DIM 2048
#define NH 16
#define NKV 4
#define NREP 4
#define ROPE_D 64
#define NOPE_D 128
#define V_D 128
#define QK_D 192
#define KV_RANK 512
#define Q_RANK 1536
#define MROWS (BB*TT)   // 4096

// ------------------------- scratch (static device memory) -------------------
__device__ float g_kv_c  [MROWS * KV_RANK];
__device__ float g_q_c   [MROWS * Q_RANK];
__device__ float g_k_nope[MROWS * (NKV*NOPE_D)];
__device__ float g_k_rope[MROWS * (NKV*ROPE_D)];
__device__ float g_v     [MROWS * (NKV*V_D)];
__device__ float g_q_nope[MROWS * (NH*NOPE_D)];
__device__ float g_q_rope[MROWS * (NH*ROPE_D)];
__device__ float g_qcat  [BB*NH  * TT * QK_D];
__device__ float g_kcat  [BB*NKV * TT * QK_D];
__device__ float g_attn  [MROWS * (NH*V_D)];

// ------------------------- tf32 tensor-core GEMM ----------------------------
// C[M,N] = A[M,K] @ B[K,N], row-major. M%128==0, N%128==0, K%32==0.
// 128x128 block tile, 32-wide K chunks, double-buffered via cp.async.
// 8 warps in 2(m) x 4(n) grid; warp tile 64x32; mma.sync m16n8k8 tf32.

#define LDA 36     // As pitch (floats), tile 128x32
#define LDB 136    // Bs pitch (floats), tile 32x128
#define ASZ (128*LDA)
#define BSZ (32*LDB)
#define GEMM_SMEM ((2*(ASZ+BSZ))*sizeof(float))

__device__ __forceinline__ uint32_t f2tf32(float x) {
    uint32_t r;
    asm("cvt.rna.tf32.f32 %0, %1;" : "=r"(r) : "f"(x));
    return r;
}

__device__ __forceinline__ void cp_async16(void* smem, const void* gmem) {
    uint32_t s = (uint32_t)__cvta_generic_to_shared(smem);
    asm volatile("cp.async.cg.shared.global [%0], [%1], 16;\n"
                 :: "r"(s), "l"(gmem));
}
__device__ __forceinline__ void cp_commit() {
    asm volatile("cp.async.commit_group;\n" ::: "memory");
}
template<int N>
__device__ __forceinline__ void cp_wait() {
    asm volatile("cp.async.wait_group %0;\n" :: "n"(N) : "memory");
}

#define MMA_TF32(c, a, b) \
    asm volatile("mma.sync.aligned.m16n8k8.row.col.f32.tf32.tf32.f32 " \
                 "{%0,%1,%2,%3},{%4,%5,%6,%7},{%8,%9},{%0,%1,%2,%3};" \
                 : "+f"((c)[0]), "+f"((c)[1]), "+f"((c)[2]), "+f"((c)[3]) \
                 : "r"((a)[0]), "r"((a)[1]), "r"((a)[2]), "r"((a)[3]), \
                   "r"((b)[0]), "r"((b)[1]))

__global__ __launch_bounds__(256) void gemm_tf32(
    const float* __restrict__ A, const float* __restrict__ B,
    float* __restrict__ C, int M, int N, int K)
{
    extern __shared__ float sm[];
    float* As = sm;               // [2][128][LDA]
    float* Bs = sm + 2 * ASZ;     // [2][32][LDB]

    const int tid  = threadIdx.x;
    const int lane = tid & 31;
    const int wid  = tid >> 5;
    const int bx = blockIdx.x, by = blockIdx.y;

    const int m0 = (wid & 1) * 64;
    const int n0 = (wid >> 1) * 32;

    // load indexing
    const int a_row = tid >> 1;            // 0..127
    const int a_col = (tid & 1) * 16;      // 0 or 16
    const int b_row = tid >> 3;            // 0..31
    const int b_col = (tid & 7) * 16;      // 0..112

    const float* Agb = A + (size_t)(by * 128 + a_row) * K + a_col;
    const float* Bgb = B + (size_t)b_row * N + bx * 128 + b_col;

    float acc[4][4][4];
    #pragma unroll
    for (int i = 0; i < 4; i++)
        #pragma unroll
        for (int j = 0; j < 4; j++)
            #pragma unroll
            for (int r = 0; r < 4; r++) acc[i][j][r] = 0.f;

    const int nch = K >> 5;

    // prologue: stage 0
    {
        float* Asb = As + a_row * LDA + a_col;
        float* Bsb = Bs + b_row * LDB + b_col;
        #pragma unroll
        for (int i = 0; i < 4; i++) cp_async16(Asb + i*4, Agb + i*4);
        #pragma unroll
        for (int i = 0; i < 4; i++) cp_async16(Bsb + i*4, Bgb + i*4);
        cp_commit();
    }

    for (int ch = 0; ch < nch; ch++) {
        if (ch + 1 < nch) {
            const int nb = (ch + 1) & 1;
            const int k0 = (ch + 1) << 5;
            float* Asb = As + nb * ASZ + a_row * LDA + a_col;
            float* Bsb = Bs + nb * BSZ + b_row * LDB + b_col;
            const float* Ag = Agb + k0;
            const float* Bg = Bgb + (size_t)k0 * N;
            #pragma unroll
            for (int i = 0; i < 4; i++) cp_async16(Asb + i*4, Ag + i*4);
            #pragma unroll
            for (int i = 0; i < 4; i++) cp_async16(Bsb + i*4, Bg + i*4);
            cp_commit();
            cp_wait<1>();
        } else {
            cp_wait<0>();
        }
        __syncthreads();

        const float* Asb = As + (ch & 1) * ASZ;
        const float* Bsb = Bs + (ch & 1) * BSZ;

        #pragma unroll
        for (int kk = 0; kk < 4; kk++) {
            uint32_t af[4][4], bf[4][2];
            const int ar = m0 + (lane >> 2);
            const int ac = kk * 8 + (lane & 3);
            #pragma unroll
            for (int mi = 0; mi < 4; mi++) {
                const int r = ar + mi * 16;
                af[mi][0] = f2tf32(Asb[r * LDA + ac]);
                af[mi][1] = f2tf32(Asb[(r + 8) * LDA + ac]);
                af[mi][2] = f2tf32(Asb[r * LDA + ac + 4]);
                af[mi][3] = f2tf32(Asb[(r + 8) * LDA + ac + 4]);
            }
            const int br = kk * 8 + (lane & 3);
            const int bc = n0 + (lane >> 2);
            #pragma unroll
            for (int ni = 0; ni < 4; ni++) {
                const int c = bc + ni * 8;
                bf[ni][0] = f2tf32(Bsb[br * LDB + c]);
                bf[ni][1] = f2tf32(Bsb[(br + 4) * LDB + c]);
            }
            #pragma unroll
            for (int mi = 0; mi < 4; mi++)
                #pragma unroll
                for (int ni = 0; ni < 4; ni++)
                    MMA_TF32(acc[mi][ni], af[mi], bf[ni]);
        }
        __syncthreads();
    }

    // epilogue
    const int crow = by * 128 + m0 + (lane >> 2);
    const int ccol = bx * 128 + n0 + (lane & 3) * 2;
    #pragma unroll
    for (int mi = 0; mi < 4; mi++) {
        #pragma unroll
        for (int ni = 0; ni < 4; ni++) {
            const int r = crow + mi * 16;
            const int c = ccol + ni * 8;
            *(float2*)(C + (size_t)r * N + c) =
                make_float2(acc[mi][ni][0], acc[mi][ni][1]);
            *(float2*)(C + (size_t)(r + 8) * N + c) =
                make_float2(acc[mi][ni][2], acc[mi][ni][3]);
        }
    }
}

// ------------------------- RoPE + assembly ----------------------------------
__device__ __forceinline__ float rope_val(const float* base, size_t rowoff,
                                          int dr, int t)
{
    int j = dr & 31;
    float theta = 1.0f / powf(10000.0f, (float)j * (1.0f / 32.0f));
    float ang = (float)t * theta;
    float c = cosf(ang), s = sinf(ang);
    float x0  = base[rowoff + dr];
    float rot = (dr < 32) ? -base[rowoff + dr + 32] : base[rowoff + dr - 32];
    return x0 * c + rot * s;
}

__global__ void assemble_q(const float* __restrict__ qn,
                           const float* __restrict__ qr,
                           float* __restrict__ qcat)
{
    size_t idx = (size_t)blockIdx.x * blockDim.x + threadIdx.x;
    const size_t total = (size_t)BB * NH * TT * QK_D;
    if (idx >= total) return;
    int d = (int)(idx % QK_D);
    size_t rem = idx / QK_D;
    int t = (int)(rem % TT); rem /= TT;
    int h = (int)(rem % NH);
    int b = (int)(rem / NH);
    size_t row = (size_t)b * TT + t;
    float val;
    if (d < NOPE_D) val = qn[row * (NH * NOPE_D) + h * NOPE_D + d];
    else            val = rope_val(qr, row * (NH * ROPE_D) + h * ROPE_D, d - NOPE_D, t);
    qcat[idx] = val;
}

__global__ void assemble_k(const float* __restrict__ kn,
                           const float* __restrict__ kr,
                           float* __restrict__ kcat)
{
    size_t idx = (size_t)blockIdx.x * blockDim.x + threadIdx.x;
    const size_t total = (size_t)BB * NKV * TT * QK_D;
    if (idx >= total) return;
    int d = (int)(idx % QK_D);
    size_t rem = idx / QK_D;
    int t = (int)(rem % TT); rem /= TT;
    int h = (int)(rem % NKV);
    int b = (int)(rem / NKV);
    size_t row = (size_t)b * TT + t;
    float val;
    if (d < NOPE_D) val = kn[row * (NKV * NOPE_D) + h * NOPE_D + d];
    else            val = rope_val(kr, row * (NKV * ROPE_D) + h * ROPE_D, d - NOPE_D, t);
    kcat[idx] = val;
}

// ------------------------- flash attention ----------------------------------
#define LDQK 68
#define LDV 132
#define LDS_S 68
#define ATTN_SMEM_FLOATS (192*LDQK*2 + 64*LDV + 64*LDS_S + 192)

__global__ __launch_bounds__(256) void flash_attn(
    const float* __restrict__ q, const float* __restrict__ k,
    const float* __restrict__ v, float* __restrict__ out)
{
    extern __shared__ float sm[];
    float* Qt   = sm;
    float* Kt   = Qt + 192 * LDQK;
    float* Vs   = Kt + 192 * LDQK;
    float* Ss   = Vs + 64 * LDV;
    float* mrow = Ss + 64 * LDS_S;
    float* lrow = mrow + 64;
    float* arow = lrow + 64;

    const int qtile = blockIdx.x;
    const int head  = blockIdx.y;
    const int b = head / NH, h = head % NH;
    const int hkv = h / NREP;
    const int tid = threadIdx.x;
    const int tx = tid & 15, ty = tid >> 4;

    const float scale = rsqrtf((float)QK_D);

    const float* qbase = q + ((size_t)head * TT + (size_t)qtile * 64) * QK_D;
    const float* kbase = k + ((size_t)(b * NKV + hkv) * TT) * QK_D;
    const float* vbase = v + (size_t)b * TT * (NKV * V_D) + hkv * V_D;

    for (int i = tid; i < 64 * QK_D; i += 256) {
        int r = i / QK_D, d = i % QK_D;
        Qt[d * LDQK + r] = qbase[(size_t)r * QK_D + d];
    }
    if (tid < 64) { mrow[tid] = -1e30f; lrow[tid] = 0.f; }

    float acc[4][8];
    #pragma unroll
    for (int i = 0; i < 4; i++)
        #pragma unroll
        for (int j = 0; j < 8; j++) acc[i][j] = 0.f;

    __syncthreads();

    const int qrow0 = qtile * 64;
    const int qr = ty * 4, kc = tx * 4;
    const int orow = ty * 4, ocol = tx * 8;
    const int srow = tid >> 2, sseg = (tid & 3) * 16;

    for (int jt = 0; jt <= qtile; jt++) {
        const int krow0 = jt * 64;
        for (int i = tid; i < 64 * QK_D; i += 256) {
            int r = i / QK_D, d = i % QK_D;
            Kt[d * LDQK + r] = kbase[(size_t)(krow0 + r) * QK_D + d];
        }
        for (int i = tid; i < 64 * V_D; i += 256) {
            int r = i / V_D, d = i % V_D;
            Vs[r * LDV + d] = vbase[(size_t)(krow0 + r) * (NKV * V_D) + d];
        }
        __syncthreads();

        float s[4][4];
        #pragma unroll
        for (int i = 0; i < 4; i++)
            #pragma unroll
            for (int j = 0; j < 4; j++) s[i][j] = 0.f;

        for (int d = 0; d < QK_D; d++) {
            float a0 = Qt[d*LDQK + qr + 0];
            float a1 = Qt[d*LDQK + qr + 1];
            float a2 = Qt[d*LDQK + qr + 2];
            float a3 = Qt[d*LDQK + qr + 3];
            float b0 = Kt[d*LDQK + kc + 0];
            float b1 = Kt[d*LDQK + kc + 1];
            float b2 = Kt[d*LDQK + kc + 2];
            float b3 = Kt[d*LDQK + kc + 3];
            s[0][0]+=a0*b0; s[0][1]+=a0*b1; s[0][2]+=a0*b2; s[0][3]+=a0*b3;
            s[1][0]+=a1*b0; s[1][1]+=a1*b1; s[1][2]+=a1*b2; s[1][3]+=a1*b3;
            s[2][0]+=a2*b0; s[2][1]+=a2*b1; s[2][2]+=a2*b2; s[2][3]+=a2*b3;
            s[3][0]+=a3*b0; s[3][1]+=a3*b1; s[3][2]+=a3*b2; s[3][3]+=a3*b3;
        }

        const bool diag = (jt == qtile);
        #pragma unroll
        for (int i = 0; i < 4; i++)
            #pragma unroll
            for (int j = 0; j < 4; j++) {
                float val = s[i][j] * scale;
                if (diag && (krow0 + kc + j > qrow0 + qr + i)) val = -1e30f;
                Ss[(qr + i) * LDS_S + kc + j] = val;
            }
        __syncthreads();

        // online softmax: each row handled by 4 lanes (16 cols each)
        {
            float mo = mrow[srow];
            float mn = mo;
            #pragma unroll
            for (int c = 0; c < 16; c++)
                mn = fmaxf(mn, Ss[srow * LDS_S + sseg + c]);
            mn = fmaxf(mn, __shfl_xor_sync(0xffffffffu, mn, 1));
            mn = fmaxf(mn, __shfl_xor_sync(0xffffffffu, mn, 2));
            float ls = 0.f;
            #pragma unroll
            for (int c = 0; c < 16; c++) {
                float p = __expf(Ss[srow * LDS_S + sseg + c] - mn);
                Ss[srow * LDS_S + sseg + c] = p;
                ls += p;
            }
            ls += __shfl_xor_sync(0xffffffffu, ls, 1);
            ls += __shfl_xor_sync(0xffffffffu, ls, 2);
            if ((tid & 3) == 0) {
                float al = __expf(mo - mn);
                mrow[srow] = mn;
                lrow[srow] = lrow[srow] * al + ls;
                arow[srow] = al;
            }
        }
        __syncthreads();

        #pragma unroll
        for (int i = 0; i < 4; i++) {
            float al = arow[orow + i];
            #pragma unroll
            for (int j = 0; j < 8; j++) acc[i][j] *= al;
        }
        for (int kk = 0; kk < 64; kk++) {
            float4 v0 = *(float4*)&Vs[kk * LDV + ocol];
            float4 v1 = *(float4*)&Vs[kk * LDV + ocol + 4];
            float vv[8] = {v0.x,v0.y,v0.z,v0.w,v1.x,v1.y,v1.z,v1.w};
            #pragma unroll
            for (int i = 0; i < 4; i++) {
                float p = Ss[(orow + i) * LDS_S + kk];
                #pragma unroll
                for (int j = 0; j < 8; j++) acc[i][j] += p * vv[j];
            }
        }
        __syncthreads();
    }

    #pragma unroll
    for (int i = 0; i < 4; i++) {
        float inv = 1.0f / lrow[orow + i];
        size_t row = (size_t)b * TT + qrow0 + orow + i;
        #pragma unroll
        for (int j = 0; j < 8; j += 4) {
            float4 o = make_float4(acc[i][j]*inv, acc[i][j+1]*inv,
                                   acc[i][j+2]*inv, acc[i][j+3]*inv);
            *(float4*)(out + row * (NH * V_D) + h * V_D + ocol + j) = o;
        }
    }
}

// ------------------------- launch -------------------------------------------
static inline dim3 gemm_grid(int M, int N) { return dim3(N / 128, M / 128); }

extern "C" void kernel_launch(void* const* d_in, const int* in_sizes, int n_in,
                              void* d_out, int out_size)
{
    const float* x         = (const float*)d_in[0];
    const float* W_kv_down = (const float*)d_in[1];
    const float* W_k_nope  = (const float*)d_in[2];
    const float* W_k_rope  = (const float*)d_in[3];
    const float* W_v       = (const float*)d_in[4];
    const float* W_q_down  = (const float*)d_in[5];
    const float* W_q_nope  = (const float*)d_in[6];
    const float* W_q_rope  = (const float*)d_in[7];
    const float* W_o       = (const float*)d_in[8];
    float* out = (float*)d_out;

    float *kv_c, *q_c, *k_nope, *k_rope, *v, *q_nope, *q_rope, *qcat, *kcat, *attn;
    cudaGetSymbolAddress((void**)&kv_c,   g_kv_c);
    cudaGetSymbolAddress((void**)&q_c,    g_q_c);
    cudaGetSymbolAddress((void**)&k_nope, g_k_nope);
    cudaGetSymbolAddress((void**)&k_rope, g_k_rope);
    cudaGetSymbolAddress((void**)&v,      g_v);
    cudaGetSymbolAddress((void**)&q_nope, g_q_nope);
    cudaGetSymbolAddress((void**)&q_rope, g_q_rope);
    cudaGetSymbolAddress((void**)&qcat,   g_qcat);
    cudaGetSymbolAddress((void**)&kcat,   g_kcat);
    cudaGetSymbolAddress((void**)&attn,   g_attn);

    cudaFuncSetAttribute(gemm_tf32, cudaFuncAttributeMaxDynamicSharedMemorySize,
                         (int)GEMM_SMEM);
    const size_t attn_smem = ATTN_SMEM_FLOATS * sizeof(float);
    cudaFuncSetAttribute(flash_attn, cudaFuncAttributeMaxDynamicSharedMemorySize,
                         (int)attn_smem);

    // down projections
    gemm_tf32<<<gemm_grid(MROWS, KV_RANK), 256, GEMM_SMEM>>>(x, W_kv_down, kv_c, MROWS, KV_RANK, DIM);
    gemm_tf32<<<gemm_grid(MROWS, Q_RANK),  256, GEMM_SMEM>>>(x, W_q_down,  q_c,  MROWS, Q_RANK,  DIM);

    // up projections
    gemm_tf32<<<gemm_grid(MROWS, NKV*NOPE_D), 256, GEMM_SMEM>>>(kv_c, W_k_nope, k_nope, MROWS, NKV*NOPE_D, KV_RANK);
    gemm_tf32<<<gemm_grid(MROWS, NKV*ROPE_D), 256, GEMM_SMEM>>>(kv_c, W_k_rope, k_rope, MROWS, NKV*ROPE_D, KV_RANK);
    gemm_tf32<<<gemm_grid(MROWS, NKV*V_D),    256, GEMM_SMEM>>>(kv_c, W_v,      v,      MROWS, NKV*V_D,    KV_RANK);
    gemm_tf32<<<gemm_grid(MROWS, NH*NOPE_D),  256, GEMM_SMEM>>>(q_c,  W_q_nope, q_nope, MROWS, NH*NOPE_D,  Q_RANK);
    gemm_tf32<<<gemm_grid(MROWS, NH*ROPE_D),  256, GEMM_SMEM>>>(q_c,  W_q_rope, q_rope, MROWS, NH*ROPE_D,  Q_RANK);

    // RoPE + layout assembly
    {
        size_t nq = (size_t)BB * NH * TT * QK_D;
        assemble_q<<<(unsigned)((nq + 255) / 256), 256>>>(q_nope, q_rope, qcat);
        size_t nk = (size_t)BB * NKV * TT * QK_D;
        assemble_k<<<(unsigned)((nk + 255) / 256), 256>>>(k_nope, k_rope, kcat);
    }

    // attention
    flash_attn<<<dim3(TT / 64, BB * NH), 256, attn_smem>>>(qcat, kcat, v, attn);

    // output projection
    gemm_tf32<<<gemm_grid(MROWS, DIM), 256, GEMM_SMEM>>>(attn, W_o, out, MROWS, DIM, NH*V_D);
}

// round 3
// speedup vs baseline: 2.3179x; 1.4476x over previous
#include <cuda_runtime.h>
#include <math.h>
#include <stdint.h>

// Problem constants
#define BB 2
#define TT 2048
#define DIM 2048
#define NH 16
#define NKV 4
#define NREP 4
#define ROPE_D 64
#define NOPE_D 128
#define V_D 128
#define QK_D 192
#define KV_RANK 512
#define Q_RANK 1536
#define MROWS (BB*TT)   // 4096

// ------------------------- scratch (static device memory) -------------------
__device__ float g_kv_c  [MROWS * KV_RANK];
__device__ float g_q_c   [MROWS * Q_RANK];
__device__ float g_k_nope[MROWS * (NKV*NOPE_D)];
__device__ float g_k_rope[MROWS * (NKV*ROPE_D)];
__device__ float g_v     [MROWS * (NKV*V_D)];
__device__ float g_q_nope[MROWS * (NH*NOPE_D)];
__device__ float g_q_rope[MROWS * (NH*ROPE_D)];
__device__ float g_qcat  [BB*NH  * TT * QK_D];
__device__ float g_kcat  [BB*NKV * TT * QK_D];
__device__ float g_attn  [MROWS * (NH*V_D)];

// ------------------------- common PTX helpers -------------------------------
__device__ __forceinline__ uint32_t f2tf32(float x) {
    uint32_t r;
    asm("cvt.rna.tf32.f32 %0, %1;" : "=r"(r) : "f"(x));
    return r;
}

__device__ __forceinline__ void cp_async16(void* smem, const void* gmem) {
    uint32_t s = (uint32_t)__cvta_generic_to_shared(smem);
    asm volatile("cp.async.cg.shared.global [%0], [%1], 16;\n"
                 :: "r"(s), "l"(gmem));
}
__device__ __forceinline__ void cp_commit() {
    asm volatile("cp.async.commit_group;\n" ::: "memory");
}
template<int N>
__device__ __forceinline__ void cp_wait() {
    asm volatile("cp.async.wait_group %0;\n" :: "n"(N) : "memory");
}

#define MMA_TF32(c, a, b) \
    asm volatile("mma.sync.aligned.m16n8k8.row.col.f32.tf32.tf32.f32 " \
                 "{%0,%1,%2,%3},{%4,%5,%6,%7},{%8,%9},{%0,%1,%2,%3};" \
                 : "+f"((c)[0]), "+f"((c)[1]), "+f"((c)[2]), "+f"((c)[3]) \
                 : "r"((a)[0]), "r"((a)[1]), "r"((a)[2]), "r"((a)[3]), \
                   "r"((b)[0]), "r"((b)[1]))

// ------------------------- tf32 tensor-core GEMM ----------------------------
// C[M,N] = A[M,K] @ B[K,N], row-major. M%128==0, N%128==0, K%32==0.
#define LDA 36
#define LDB 136
#define ASZ (128*LDA)
#define BSZ (32*LDB)
#define GEMM_SMEM ((2*(ASZ+BSZ))*sizeof(float))

__global__ __launch_bounds__(256) void gemm_tf32(
    const float* __restrict__ A, const float* __restrict__ B,
    float* __restrict__ C, int M, int N, int K)
{
    extern __shared__ float sm[];
    float* As = sm;
    float* Bs = sm + 2 * ASZ;

    const int tid  = threadIdx.x;
    const int lane = tid & 31;
    const int wid  = tid >> 5;
    const int bx = blockIdx.x, by = blockIdx.y;

    const int m0 = (wid & 1) * 64;
    const int n0 = (wid >> 1) * 32;

    const int a_row = tid >> 1;
    const int a_col = (tid & 1) * 16;
    const int b_row = tid >> 3;
    const int b_col = (tid & 7) * 16;

    const float* Agb = A + (size_t)(by * 128 + a_row) * K + a_col;
    const float* Bgb = B + (size_t)b_row * N + bx * 128 + b_col;

    float acc[4][4][4];
    #pragma unroll
    for (int i = 0; i < 4; i++)
        #pragma unroll
        for (int j = 0; j < 4; j++)
            #pragma unroll
            for (int r = 0; r < 4; r++) acc[i][j][r] = 0.f;

    const int nch = K >> 5;

    {
        float* Asb = As + a_row * LDA + a_col;
        float* Bsb = Bs + b_row * LDB + b_col;
        #pragma unroll
        for (int i = 0; i < 4; i++) cp_async16(Asb + i*4, Agb + i*4);
        #pragma unroll
        for (int i = 0; i < 4; i++) cp_async16(Bsb + i*4, Bgb + i*4);
        cp_commit();
    }

    for (int ch = 0; ch < nch; ch++) {
        if (ch + 1 < nch) {
            const int nb = (ch + 1) & 1;
            const int k0 = (ch + 1) << 5;
            float* Asb = As + nb * ASZ + a_row * LDA + a_col;
            float* Bsb = Bs + nb * BSZ + b_row * LDB + b_col;
            const float* Ag = Agb + k0;
            const float* Bg = Bgb + (size_t)k0 * N;
            #pragma unroll
            for (int i = 0; i < 4; i++) cp_async16(Asb + i*4, Ag + i*4);
            #pragma unroll
            for (int i = 0; i < 4; i++) cp_async16(Bsb + i*4, Bg + i*4);
            cp_commit();
            cp_wait<1>();
        } else {
            cp_wait<0>();
        }
        __syncthreads();

        const float* Asb = As + (ch & 1) * ASZ;
        const float* Bsb = Bs + (ch & 1) * BSZ;

        #pragma unroll
        for (int kk = 0; kk < 4; kk++) {
            uint32_t af[4][4], bf[4][2];
            const int ar = m0 + (lane >> 2);
            const int ac = kk * 8 + (lane & 3);
            #pragma unroll
            for (int mi = 0; mi < 4; mi++) {
                const int r = ar + mi * 16;
                af[mi][0] = f2tf32(Asb[r * LDA + ac]);
                af[mi][1] = f2tf32(Asb[(r + 8) * LDA + ac]);
                af[mi][2] = f2tf32(Asb[r * LDA + ac + 4]);
                af[mi][3] = f2tf32(Asb[(r + 8) * LDA + ac + 4]);
            }
            const int br = kk * 8 + (lane & 3);
            const int bc = n0 + (lane >> 2);
            #pragma unroll
            for (int ni = 0; ni < 4; ni++) {
                const int c = bc + ni * 8;
                bf[ni][0] = f2tf32(Bsb[br * LDB + c]);
                bf[ni][1] = f2tf32(Bsb[(br + 4) * LDB + c]);
            }
            #pragma unroll
            for (int mi = 0; mi < 4; mi++)
                #pragma unroll
                for (int ni = 0; ni < 4; ni++)
                    MMA_TF32(acc[mi][ni], af[mi], bf[ni]);
        }
        __syncthreads();
    }

    const int crow = by * 128 + m0 + (lane >> 2);
    const int ccol = bx * 128 + n0 + (lane & 3) * 2;
    #pragma unroll
    for (int mi = 0; mi < 4; mi++) {
        #pragma unroll
        for (int ni = 0; ni < 4; ni++) {
            const int r = crow + mi * 16;
            const int c = ccol + ni * 8;
            *(float2*)(C + (size_t)r * N + c) =
                make_float2(acc[mi][ni][0], acc[mi][ni][1]);
            *(float2*)(C + (size_t)(r + 8) * N + c) =
                make_float2(acc[mi][ni][2], acc[mi][ni][3]);
        }
    }
}

// ------------------------- RoPE + assembly ----------------------------------
__device__ __forceinline__ float rope_val(const float* base, size_t rowoff,
                                          int dr, int t)
{
    int j = dr & 31;
    float theta = 1.0f / powf(10000.0f, (float)j * (1.0f / 32.0f));
    float ang = (float)t * theta;
    float c = cosf(ang), s = sinf(ang);
    float x0  = base[rowoff + dr];
    float rot = (dr < 32) ? -base[rowoff + dr + 32] : base[rowoff + dr - 32];
    return x0 * c + rot * s;
}

__global__ void assemble_q(const float* __restrict__ qn,
                           const float* __restrict__ qr,
                           float* __restrict__ qcat)
{
    size_t idx = (size_t)blockIdx.x * blockDim.x + threadIdx.x;
    const size_t total = (size_t)BB * NH * TT * QK_D;
    if (idx >= total) return;
    int d = (int)(idx % QK_D);
    size_t rem = idx / QK_D;
    int t = (int)(rem % TT); rem /= TT;
    int h = (int)(rem % NH);
    int b = (int)(rem / NH);
    size_t row = (size_t)b * TT + t;
    float val;
    if (d < NOPE_D) val = qn[row * (NH * NOPE_D) + h * NOPE_D + d];
    else            val = rope_val(qr, row * (NH * ROPE_D) + h * ROPE_D, d - NOPE_D, t);
    qcat[idx] = val;
}

__global__ void assemble_k(const float* __restrict__ kn,
                           const float* __restrict__ kr,
                           float* __restrict__ kcat)
{
    size_t idx = (size_t)blockIdx.x * blockDim.x + threadIdx.x;
    const size_t total = (size_t)BB * NKV * TT * QK_D;
    if (idx >= total) return;
    int d = (int)(idx % QK_D);
    size_t rem = idx / QK_D;
    int t = (int)(rem % TT); rem /= TT;
    int h = (int)(rem % NKV);
    int b = (int)(rem / NKV);
    size_t row = (size_t)b * TT + t;
    float val;
    if (d < NOPE_D) val = kn[row * (NKV * NOPE_D) + h * NOPE_D + d];
    else            val = rope_val(kr, row * (NKV * ROPE_D) + h * ROPE_D, d - NOPE_D, t);
    kcat[idx] = val;
}

// ------------------------- flash attention (tf32 mma) -----------------------
// Block: 256 threads (8 warps). Q-tile 128 rows (warp w -> rows 16w..16w+15),
// K-tile 64 rows per iteration. Online softmax entirely in registers
// (mma C-fragment layout: 4 lanes per row -> shfl_xor reduce).
// P round-trips through smem (warp-private rows -> __syncwarp only).
#define LQ 196      // 192 + 4  -> +4 banks per row: conflict-free frag loads
#define LK 196
#define LV 136      // 128 + 8  -> +8 banks per row: conflict-free B-frag loads
#define LP 68       // 64 + 4
#define QS_SZ (128*LQ)
#define KS_SZ (64*LK)
#define VS_SZ (64*LV)
#define PS_SZ (128*LP)
#define ATTN_SMEM ((QS_SZ + KS_SZ + VS_SZ + PS_SZ) * sizeof(uint32_t))

__global__ __launch_bounds__(256) void flash_attn_mma(
    const float* __restrict__ q, const float* __restrict__ k,
    const float* __restrict__ v, float* __restrict__ out)
{
    extern __shared__ uint32_t su[];
    uint32_t* Qs = su;
    uint32_t* Ks = su + QS_SZ;
    uint32_t* Vs = Ks + KS_SZ;
    uint32_t* Ps = Vs + VS_SZ;

    const int qi   = blockIdx.x;
    const int head = blockIdx.y;
    const int b = head / NH, h = head % NH;
    const int hkv = h / NREP;
    const int tid = threadIdx.x;
    const int lane = tid & 31, wid = tid >> 5;
    const int r = lane >> 2, t = lane & 3;
    const int qw = wid * 16;
    const int qrow0 = qi * 128;
    const float scale = rsqrtf((float)QK_D);

    const float* qbase = q + ((size_t)head * TT + qrow0) * QK_D;
    const float* kbase = k + ((size_t)(b * NKV + hkv) * TT) * QK_D;
    const float* vbase = v + (size_t)b * TT * (NKV * V_D) + hkv * V_D;

    // Q (pre-scaled) -> smem tf32
    for (int i = tid; i < 128 * QK_D; i += 256) {
        int rr = i / QK_D, c = i % QK_D;
        Qs[rr * LQ + c] = f2tf32(qbase[(size_t)rr * QK_D + c] * scale);
    }

    float m0 = -1e30f, m1 = -1e30f, l0 = 0.f, l1 = 0.f;
    float oacc[16][4];
    #pragma unroll
    for (int j = 0; j < 16; j++)
        #pragma unroll
        for (int c = 0; c < 4; c++) oacc[j][c] = 0.f;

    __syncthreads();

    const int niter = 2 * qi + 2;
    for (int jt = 0; jt < niter; jt++) {
        const int krow0 = jt * 64;

        for (int i = tid; i < 64 * QK_D; i += 256) {
            int rr = i / QK_D, c = i % QK_D;
            Ks[rr * LK + c] = f2tf32(kbase[(size_t)(krow0 + rr) * QK_D + c]);
        }
        for (int i = tid; i < 64 * V_D; i += 256) {
            int rr = i >> 7, c = i & 127;
            Vs[rr * LV + c] = f2tf32(vbase[(size_t)(krow0 + rr) * (NKV * V_D) + c]);
        }
        __syncthreads();

        // ---- S = Q @ K^T  (per warp: 16 x 64) ----
        float sacc[8][4];
        #pragma unroll
        for (int j = 0; j < 8; j++)
            #pragma unroll
            for (int c = 0; c < 4; c++) sacc[j][c] = 0.f;

        #pragma unroll 4
        for (int kc = 0; kc < 24; kc++) {
            uint32_t a[4];
            const uint32_t* qp = Qs + (qw + r) * LQ + kc * 8 + t;
            a[0] = qp[0]; a[1] = qp[8 * LQ]; a[2] = qp[4]; a[3] = qp[8 * LQ + 4];
            #pragma unroll
            for (int j = 0; j < 8; j++) {
                uint32_t bf[2];
                const uint32_t* kp = Ks + (8 * j + r) * LK + kc * 8 + t;
                bf[0] = kp[0]; bf[1] = kp[4];
                MMA_TF32(sacc[j], a, bf);
            }
        }

        // ---- mask + online softmax (registers + shfl) ----
        const int gr0 = qrow0 + qw + r;       // this thread's row (and gr0+8)
        const bool need_mask = (jt >= 2 * qi);
        float mx0 = m0, mx1 = m1;
        #pragma unroll
        for (int j = 0; j < 8; j++) {
            if (need_mask) {
                int gc = krow0 + 8 * j + 2 * t;
                if (gc     > gr0)     sacc[j][0] = -1e30f;
                if (gc + 1 > gr0)     sacc[j][1] = -1e30f;
                if (gc     > gr0 + 8) sacc[j][2] = -1e30f;
                if (gc + 1 > gr0 + 8) sacc[j][3] = -1e30f;
            }
            mx0 = fmaxf(mx0, fmaxf(sacc[j][0], sacc[j][1]));
            mx1 = fmaxf(mx1, fmaxf(sacc[j][2], sacc[j][3]));
        }
        mx0 = fmaxf(mx0, __shfl_xor_sync(0xffffffffu, mx0, 1));
        mx0 = fmaxf(mx0, __shfl_xor_sync(0xffffffffu, mx0, 2));
        mx1 = fmaxf(mx1, __shfl_xor_sync(0xffffffffu, mx1, 1));
        mx1 = fmaxf(mx1, __shfl_xor_sync(0xffffffffu, mx1, 2));

        float alpha0 = __expf(m0 - mx0);
        float alpha1 = __expf(m1 - mx1);
        m0 = mx0; m1 = mx1;

        float ls0 = 0.f, ls1 = 0.f;
        uint32_t* pp = Ps + (qw + r) * LP;
        #pragma unroll
        for (int j = 0; j < 8; j++) {
            float p0 = __expf(sacc[j][0] - mx0);
            float p1 = __expf(sacc[j][1] - mx0);
            float p2 = __expf(sacc[j][2] - mx1);
            float p3 = __expf(sacc[j][3] - mx1);
            ls0 += p0 + p1; ls1 += p2 + p3;
            pp[8 * j + 2 * t]          = f2tf32(p0);
            pp[8 * j + 2 * t + 1]      = f2tf32(p1);
            pp[8 * LP + 8 * j + 2 * t]     = f2tf32(p2);
            pp[8 * LP + 8 * j + 2 * t + 1] = f2tf32(p3);
        }
        ls0 += __shfl_xor_sync(0xffffffffu, ls0, 1);
        ls0 += __shfl_xor_sync(0xffffffffu, ls0, 2);
        ls1 += __shfl_xor_sync(0xffffffffu, ls1, 1);
        ls1 += __shfl_xor_sync(0xffffffffu, ls1, 2);
        l0 = l0 * alpha0 + ls0;
        l1 = l1 * alpha1 + ls1;

        #pragma unroll
        for (int j = 0; j < 16; j++) {
            oacc[j][0] *= alpha0; oacc[j][1] *= alpha0;
            oacc[j][2] *= alpha1; oacc[j][3] *= alpha1;
        }
        __syncwarp();   // P rows are warp-private

        // ---- O += P @ V  (per warp: 16 x 128) ----
        #pragma unroll
        for (int kc = 0; kc < 8; kc++) {
            uint32_t a[4];
            const uint32_t* ap = Ps + (qw + r) * LP + kc * 8 + t;
            a[0] = ap[0]; a[1] = ap[8 * LP]; a[2] = ap[4]; a[3] = ap[8 * LP + 4];
            #pragma unroll
            for (int j = 0; j < 16; j++) {
                uint32_t bf[2];
                const uint32_t* vp = Vs + (kc * 8 + t) * LV + 8 * j + r;
                bf[0] = vp[0]; bf[1] = vp[4 * LV];
                MMA_TF32(oacc[j], a, bf);
            }
        }
        __syncthreads();   // before next iteration overwrites Ks/Vs
    }

    // ---- epilogue: normalize + store [B,T,H*V_D] ----
    const float inv0 = 1.0f / l0;
    const float inv1 = 1.0f / l1;
    const int gr0 = qrow0 + qw + r;
    float* ob = out + ((size_t)b * TT + gr0) * (NH * V_D) + h * V_D;
    #pragma unroll
    for (int j = 0; j < 16; j++) {
        int c = 8 * j + 2 * t;
        *(float2*)(ob + c) =
            make_float2(oacc[j][0] * inv0, oacc[j][1] * inv0);
        *(float2*)(ob + (size_t)8 * (NH * V_D) + c) =
            make_float2(oacc[j][2] * inv1, oacc[j][3] * inv1);
    }
}

// ------------------------- launch -------------------------------------------
static inline dim3 gemm_grid(int M, int N) { return dim3(N / 128, M / 128); }

extern "C" void kernel_launch(void* const* d_in, const int* in_sizes, int n_in,
                              void* d_out, int out_size)
{
    const float* x         = (const float*)d_in[0];
    const float* W_kv_down = (const float*)d_in[1];
    const float* W_k_nope  = (const float*)d_in[2];
    const float* W_k_rope  = (const float*)d_in[3];
    const float* W_v       = (const float*)d_in[4];
    const float* W_q_down  = (const float*)d_in[5];
    const float* W_q_nope  = (const float*)d_in[6];
    const float* W_q_rope  = (const float*)d_in[7];
    const float* W_o       = (const float*)d_in[8];
    float* out = (float*)d_out;

    float *kv_c, *q_c, *k_nope, *k_rope, *v, *q_nope, *q_rope, *qcat, *kcat, *attn;
    cudaGetSymbolAddress((void**)&kv_c,   g_kv_c);
    cudaGetSymbolAddress((void**)&q_c,    g_q_c);
    cudaGetSymbolAddress((void**)&k_nope, g_k_nope);
    cudaGetSymbolAddress((void**)&k_rope, g_k_rope);
    cudaGetSymbolAddress((void**)&v,      g_v);
    cudaGetSymbolAddress((void**)&q_nope, g_q_nope);
    cudaGetSymbolAddress((void**)&q_rope, g_q_rope);
    cudaGetSymbolAddress((void**)&qcat,   g_qcat);
    cudaGetSymbolAddress((void**)&kcat,   g_kcat);
    cudaGetSymbolAddress((void**)&attn,   g_attn);

    cudaFuncSetAttribute(gemm_tf32, cudaFuncAttributeMaxDynamicSharedMemorySize,
                         (int)GEMM_SMEM);
    cudaFuncSetAttribute(flash_attn_mma, cudaFuncAttributeMaxDynamicSharedMemorySize,
                         (int)ATTN_SMEM);

    // down projections
    gemm_tf32<<<gemm_grid(MROWS, KV_RANK), 256, GEMM_SMEM>>>(x, W_kv_down, kv_c, MROWS, KV_RANK, DIM);
    gemm_tf32<<<gemm_grid(MROWS, Q_RANK),  256, GEMM_SMEM>>>(x, W_q_down,  q_c,  MROWS, Q_RANK,  DIM);

    // up projections
    gemm_tf32<<<gemm_grid(MROWS, NKV*NOPE_D), 256, GEMM_SMEM>>>(kv_c, W_k_nope, k_nope, MROWS, NKV*NOPE_D, KV_RANK);
    gemm_tf32<<<gemm_grid(MROWS, NKV*ROPE_D), 256, GEMM_SMEM>>>(kv_c, W_k_rope, k_rope, MROWS, NKV*ROPE_D, KV_RANK);
    gemm_tf32<<<gemm_grid(MROWS, NKV*V_D),    256, GEMM_SMEM>>>(kv_c, W_v,      v,      MROWS, NKV*V_D,    KV_RANK);
    gemm_tf32<<<gemm_grid(MROWS, NH*NOPE_D),  256, GEMM_SMEM>>>(q_c,  W_q_nope, q_nope, MROWS, NH*NOPE_D,  Q_RANK);
    gemm_tf32<<<gemm_grid(MROWS, NH*ROPE_D),  256, GEMM_SMEM>>>(q_c,  W_q_rope, q_rope, MROWS, NH*ROPE_D,  Q_RANK);

    // RoPE + layout assembly
    {
        size_t nq = (size_t)BB * NH * TT * QK_D;
        assemble_q<<<(unsigned)((nq + 255) / 256), 256>>>(q_nope, q_rope, qcat);
        size_t nk = (size_t)BB * NKV * TT * QK_D;
        assemble_k<<<(unsigned)((nk + 255) / 256), 256>>>(k_nope, k_rope, kcat);
    }

    // attention (tensor-core)
    flash_attn_mma<<<dim3(TT / 128, BB * NH), 256, ATTN_SMEM>>>(qcat, kcat, v, attn);

    // output projection
    gemm_tf32<<<gemm_grid(MROWS, DIM), 256, GEMM_SMEM>>>(attn, W_o, out, MROWS, DIM, NH*V_D);
}

// round 4
// speedup vs baseline: 2.5139x; 1.0846x over previous
#include <cuda_runtime.h>
#include <math.h>
#include <stdint.h>

// Problem constants
#define BB 2
#define TT 2048
#define DIM 2048
#define NH 16
#define NKV 4
#define NREP 4
#define ROPE_D 64
#define NOPE_D 128
#define V_D 128
#define QK_D 192
#define KV_RANK 512
#define Q_RANK 1536
#define MROWS (BB*TT)   // 4096

// fused widths
#define N_DOWN 2048            // [kv_c(512) | q_c(1536)]
#define N_KVUP 1280            // [k_nope(512) | k_rope(256) | v(512)]
#define N_QUP  3072            // [q_nope(2048) | q_rope(1024)]

// ------------------------- scratch (static device memory) -------------------
__device__ float g_w_down[DIM * N_DOWN];        // rounded concat weights
__device__ float g_w_kv  [KV_RANK * N_KVUP];
__device__ float g_w_q   [Q_RANK * N_QUP];
__device__ float g_w_o   [NH*V_D * DIM];
__device__ float g_x_r   [MROWS * DIM];         // tf32-rounded x
__device__ float g_cdown [MROWS * N_DOWN];      // [kv_c | q_c] (tf32-rounded)
__device__ float g_kvup  [MROWS * N_KVUP];      // [k_nope | k_rope | v]
__device__ float g_qup   [MROWS * N_QUP];       // [q_nope | q_rope]
__device__ float g_qcat  [BB*NH  * TT * QK_D];
__device__ float g_kcat  [BB*NKV * TT * QK_D];
__device__ float g_attn  [MROWS * (NH*V_D)];    // tf32-rounded

// ------------------------- common PTX helpers -------------------------------
__device__ __forceinline__ uint32_t f2tf32(float x) {
    uint32_t r;
    asm("cvt.rna.tf32.f32 %0, %1;" : "=r"(r) : "f"(x));
    return r;
}
__device__ __forceinline__ float roundtf(float x) {
    return __uint_as_float(f2tf32(x));
}

__device__ __forceinline__ void cp_async16(void* smem, const void* gmem) {
    uint32_t s = (uint32_t)__cvta_generic_to_shared(smem);
    asm volatile("cp.async.cg.shared.global [%0], [%1], 16;\n"
                 :: "r"(s), "l"(gmem));
}
__device__ __forceinline__ void cp_commit() {
    asm volatile("cp.async.commit_group;\n" ::: "memory");
}
template<int N>
__device__ __forceinline__ void cp_wait() {
    asm volatile("cp.async.wait_group %0;\n" :: "n"(N) : "memory");
}

#define MMA_TF32(c, a, b) \
    asm volatile("mma.sync.aligned.m16n8k8.row.col.f32.tf32.tf32.f32 " \
                 "{%0,%1,%2,%3},{%4,%5,%6,%7},{%8,%9},{%0,%1,%2,%3};" \
                 : "+f"((c)[0]), "+f"((c)[1]), "+f"((c)[2]), "+f"((c)[3]) \
                 : "r"((a)[0]), "r"((a)[1]), "r"((a)[2]), "r"((a)[3]), \
                   "r"((b)[0]), "r"((b)[1]))

// ------------------------- weight concat + tf32 rounding --------------------
// dst[r*dld4 + doff4 + c] = round(src[r*cols4 + c]) ; all in float4 units
__global__ void copy_round4(float4* __restrict__ dst, const float4* __restrict__ src,
                            int rows, int cols4, int dld4, int doff4)
{
    int total = rows * cols4;
    for (int i = blockIdx.x * blockDim.x + threadIdx.x; i < total;
         i += gridDim.x * blockDim.x) {
        int r = i / cols4, c = i % cols4;
        float4 v = src[i];
        v.x = roundtf(v.x); v.y = roundtf(v.y);
        v.z = roundtf(v.z); v.w = roundtf(v.w);
        dst[(size_t)r * dld4 + doff4 + c] = v;
    }
}

// ------------------------- tf32 tensor-core GEMM ----------------------------
// C[M,N] = A[M,K] @ B[K,N]; A row stride lda; B/C row stride N.
// Inputs must be pre-rounded to tf32. Optionally round C on store.
#define LDA 36
#define LDB 136
#define ASZ (128*LDA)
#define BSZ (32*LDB)
#define GEMM_SMEM ((2*(ASZ+BSZ))*sizeof(float))

__global__ __launch_bounds__(256, 2) void gemm_tf32(
    const float* __restrict__ A, int lda,
    const float* __restrict__ B,
    float* __restrict__ C, int N, int K, int round_c)
{
    extern __shared__ float sm[];
    float* As = sm;
    float* Bs = sm + 2 * ASZ;

    const int tid  = threadIdx.x;
    const int lane = tid & 31;
    const int wid  = tid >> 5;
    const int bx = blockIdx.x, by = blockIdx.y;

    const int m0 = (wid & 1) * 64;
    const int n0 = (wid >> 1) * 32;

    const int a_row = tid >> 1;
    const int a_col = (tid & 1) * 16;
    const int b_row = tid >> 3;
    const int b_col = (tid & 7) * 16;

    const float* Agb = A + (size_t)(by * 128 + a_row) * lda + a_col;
    const float* Bgb = B + (size_t)b_row * N + bx * 128 + b_col;

    float acc[4][4][4];
    #pragma unroll
    for (int i = 0; i < 4; i++)
        #pragma unroll
        for (int j = 0; j < 4; j++)
            #pragma unroll
            for (int r = 0; r < 4; r++) acc[i][j][r] = 0.f;

    const int nch = K >> 5;

    {
        float* Asb = As + a_row * LDA + a_col;
        float* Bsb = Bs + b_row * LDB + b_col;
        #pragma unroll
        for (int i = 0; i < 4; i++) cp_async16(Asb + i*4, Agb + i*4);
        #pragma unroll
        for (int i = 0; i < 4; i++) cp_async16(Bsb + i*4, Bgb + i*4);
        cp_commit();
    }

    for (int ch = 0; ch < nch; ch++) {
        if (ch + 1 < nch) {
            const int nb = (ch + 1) & 1;
            const int k0 = (ch + 1) << 5;
            float* Asb = As + nb * ASZ + a_row * LDA + a_col;
            float* Bsb = Bs + nb * BSZ + b_row * LDB + b_col;
            const float* Ag = Agb + k0;
            const float* Bg = Bgb + (size_t)k0 * N;
            #pragma unroll
            for (int i = 0; i < 4; i++) cp_async16(Asb + i*4, Ag + i*4);
            #pragma unroll
            for (int i = 0; i < 4; i++) cp_async16(Bsb + i*4, Bg + i*4);
            cp_commit();
            cp_wait<1>();
        } else {
            cp_wait<0>();
        }
        __syncthreads();

        const uint32_t* Asb = (const uint32_t*)(As + (ch & 1) * ASZ);
        const uint32_t* Bsb = (const uint32_t*)(Bs + (ch & 1) * BSZ);

        #pragma unroll
        for (int kk = 0; kk < 4; kk++) {
            uint32_t af[4][4], bf[4][2];
            const int ar = m0 + (lane >> 2);
            const int ac = kk * 8 + (lane & 3);
            #pragma unroll
            for (int mi = 0; mi < 4; mi++) {
                const int r = ar + mi * 16;
                af[mi][0] = Asb[r * LDA + ac];
                af[mi][1] = Asb[(r + 8) * LDA + ac];
                af[mi][2] = Asb[r * LDA + ac + 4];
                af[mi][3] = Asb[(r + 8) * LDA + ac + 4];
            }
            const int br = kk * 8 + (lane & 3);
            const int bc = n0 + (lane >> 2);
            #pragma unroll
            for (int ni = 0; ni < 4; ni++) {
                const int c = bc + ni * 8;
                bf[ni][0] = Bsb[br * LDB + c];
                bf[ni][1] = Bsb[(br + 4) * LDB + c];
            }
            #pragma unroll
            for (int mi = 0; mi < 4; mi++)
                #pragma unroll
                for (int ni = 0; ni < 4; ni++)
                    MMA_TF32(acc[mi][ni], af[mi], bf[ni]);
        }
        __syncthreads();
    }

    const int crow = by * 128 + m0 + (lane >> 2);
    const int ccol = bx * 128 + n0 + (lane & 3) * 2;
    #pragma unroll
    for (int mi = 0; mi < 4; mi++) {
        #pragma unroll
        for (int ni = 0; ni < 4; ni++) {
            const int r = crow + mi * 16;
            const int c = ccol + ni * 8;
            float v0 = acc[mi][ni][0], v1 = acc[mi][ni][1];
            float v2 = acc[mi][ni][2], v3 = acc[mi][ni][3];
            if (round_c) {
                v0 = roundtf(v0); v1 = roundtf(v1);
                v2 = roundtf(v2); v3 = roundtf(v3);
            }
            *(float2*)(C + (size_t)r * N + c) = make_float2(v0, v1);
            *(float2*)(C + (size_t)(r + 8) * N + c) = make_float2(v2, v3);
        }
    }
}

// ------------------------- RoPE + assembly ----------------------------------
__device__ __forceinline__ float rope_val(const float* base, size_t rowoff,
                                          int dr, int t)
{
    int j = dr & 31;
    float theta = 1.0f / powf(10000.0f, (float)j * (1.0f / 32.0f));
    float ang = (float)t * theta;
    float c = cosf(ang), s = sinf(ang);
    float x0  = base[rowoff + dr];
    float rot = (dr < 32) ? -base[rowoff + dr + 32] : base[rowoff + dr - 32];
    return x0 * c + rot * s;
}

__global__ void assemble_q(const float* __restrict__ qn, int qnld,
                           const float* __restrict__ qr, int qrld,
                           float* __restrict__ qcat)
{
    size_t idx = (size_t)blockIdx.x * blockDim.x + threadIdx.x;
    const size_t total = (size_t)BB * NH * TT * QK_D;
    if (idx >= total) return;
    int d = (int)(idx % QK_D);
    size_t rem = idx / QK_D;
    int t = (int)(rem % TT); rem /= TT;
    int h = (int)(rem % NH);
    int b = (int)(rem / NH);
    size_t row = (size_t)b * TT + t;
    float val;
    if (d < NOPE_D) val = qn[row * qnld + h * NOPE_D + d];
    else            val = rope_val(qr, row * qrld + h * ROPE_D, d - NOPE_D, t);
    qcat[idx] = val;
}

__global__ void assemble_k(const float* __restrict__ kn, int knld,
                           const float* __restrict__ kr, int krld,
                           float* __restrict__ kcat)
{
    size_t idx = (size_t)blockIdx.x * blockDim.x + threadIdx.x;
    const size_t total = (size_t)BB * NKV * TT * QK_D;
    if (idx >= total) return;
    int d = (int)(idx % QK_D);
    size_t rem = idx / QK_D;
    int t = (int)(rem % TT); rem /= TT;
    int h = (int)(rem % NKV);
    int b = (int)(rem / NKV);
    size_t row = (size_t)b * TT + t;
    float val;
    if (d < NOPE_D) val = kn[row * knld + h * NOPE_D + d];
    else            val = rope_val(kr, row * krld + h * ROPE_D, d - NOPE_D, t);
    kcat[idx] = val;
}

// ------------------------- flash attention (tf32 mma) -----------------------
#define LQ 196
#define LK 196
#define LV 136
#define LP 68
#define VLD N_KVUP          // v row stride inside g_kvup
#define QS_SZ (128*LQ)
#define KS_SZ (64*LK)
#define VS_SZ (64*LV)
#define PS_SZ (128*LP)
#define ATTN_SMEM ((QS_SZ + KS_SZ + VS_SZ + PS_SZ) * sizeof(uint32_t))

__global__ __launch_bounds__(256) void flash_attn_mma(
    const float* __restrict__ q, const float* __restrict__ k,
    const float* __restrict__ v, float* __restrict__ out)
{
    extern __shared__ uint32_t su[];
    uint32_t* Qs = su;
    uint32_t* Ks = su + QS_SZ;
    uint32_t* Vs = Ks + KS_SZ;
    uint32_t* Ps = Vs + VS_SZ;

    const int qi   = blockIdx.x;
    const int head = blockIdx.y;
    const int b = head / NH, h = head % NH;
    const int hkv = h / NREP;
    const int tid = threadIdx.x;
    const int lane = tid & 31, wid = tid >> 5;
    const int r = lane >> 2, t = lane & 3;
    const int qw = wid * 16;
    const int qrow0 = qi * 128;
    const float scale = rsqrtf((float)QK_D);

    const float* qbase = q + ((size_t)head * TT + qrow0) * QK_D;
    const float* kbase = k + ((size_t)(b * NKV + hkv) * TT) * QK_D;
    const float* vbase = v + (size_t)b * TT * VLD + hkv * V_D;

    for (int i = tid; i < 128 * QK_D; i += 256) {
        int rr = i / QK_D, c = i % QK_D;
        Qs[rr * LQ + c] = f2tf32(qbase[(size_t)rr * QK_D + c] * scale);
    }

    float m0 = -1e30f, m1 = -1e30f, l0 = 0.f, l1 = 0.f;
    float oacc[16][4];
    #pragma unroll
    for (int j = 0; j < 16; j++)
        #pragma unroll
        for (int c = 0; c < 4; c++) oacc[j][c] = 0.f;

    __syncthreads();

    const int niter = 2 * qi + 2;
    for (int jt = 0; jt < niter; jt++) {
        const int krow0 = jt * 64;

        for (int i = tid; i < 64 * QK_D; i += 256) {
            int rr = i / QK_D, c = i % QK_D;
            Ks[rr * LK + c] = f2tf32(kbase[(size_t)(krow0 + rr) * QK_D + c]);
        }
        for (int i = tid; i < 64 * V_D; i += 256) {
            int rr = i >> 7, c = i & 127;
            Vs[rr * LV + c] = f2tf32(vbase[(size_t)(krow0 + rr) * VLD + c]);
        }
        __syncthreads();

        // ---- S = Q @ K^T ----
        float sacc[8][4];
        #pragma unroll
        for (int j = 0; j < 8; j++)
            #pragma unroll
            for (int c = 0; c < 4; c++) sacc[j][c] = 0.f;

        #pragma unroll 4
        for (int kc = 0; kc < 24; kc++) {
            uint32_t a[4];
            const uint32_t* qp = Qs + (qw + r) * LQ + kc * 8 + t;
            a[0] = qp[0]; a[1] = qp[8 * LQ]; a[2] = qp[4]; a[3] = qp[8 * LQ + 4];
            #pragma unroll
            for (int j = 0; j < 8; j++) {
                uint32_t bf[2];
                const uint32_t* kp = Ks + (8 * j + r) * LK + kc * 8 + t;
                bf[0] = kp[0]; bf[1] = kp[4];
                MMA_TF32(sacc[j], a, bf);
            }
        }

        // ---- mask + online softmax ----
        const int gr0 = qrow0 + qw + r;
        const bool need_mask = (jt >= 2 * qi);
        float mx0 = m0, mx1 = m1;
        #pragma unroll
        for (int j = 0; j < 8; j++) {
            if (need_mask) {
                int gc = krow0 + 8 * j + 2 * t;
                if (gc     > gr0)     sacc[j][0] = -1e30f;
                if (gc + 1 > gr0)     sacc[j][1] = -1e30f;
                if (gc     > gr0 + 8) sacc[j][2] = -1e30f;
                if (gc + 1 > gr0 + 8) sacc[j][3] = -1e30f;
            }
            mx0 = fmaxf(mx0, fmaxf(sacc[j][0], sacc[j][1]));
            mx1 = fmaxf(mx1, fmaxf(sacc[j][2], sacc[j][3]));
        }
        mx0 = fmaxf(mx0, __shfl_xor_sync(0xffffffffu, mx0, 1));
        mx0 = fmaxf(mx0, __shfl_xor_sync(0xffffffffu, mx0, 2));
        mx1 = fmaxf(mx1, __shfl_xor_sync(0xffffffffu, mx1, 1));
        mx1 = fmaxf(mx1, __shfl_xor_sync(0xffffffffu, mx1, 2));

        float alpha0 = __expf(m0 - mx0);
        float alpha1 = __expf(m1 - mx1);
        m0 = mx0; m1 = mx1;

        float ls0 = 0.f, ls1 = 0.f;
        uint32_t* pp = Ps + (qw + r) * LP;
        #pragma unroll
        for (int j = 0; j < 8; j++) {
            float p0 = __expf(sacc[j][0] - mx0);
            float p1 = __expf(sacc[j][1] - mx0);
            float p2 = __expf(sacc[j][2] - mx1);
            float p3 = __expf(sacc[j][3] - mx1);
            ls0 += p0 + p1; ls1 += p2 + p3;
            pp[8 * j + 2 * t]          = f2tf32(p0);
            pp[8 * j + 2 * t + 1]      = f2tf32(p1);
            pp[8 * LP + 8 * j + 2 * t]     = f2tf32(p2);
            pp[8 * LP + 8 * j + 2 * t + 1] = f2tf32(p3);
        }
        ls0 += __shfl_xor_sync(0xffffffffu, ls0, 1);
        ls0 += __shfl_xor_sync(0xffffffffu, ls0, 2);
        ls1 += __shfl_xor_sync(0xffffffffu, ls1, 1);
        ls1 += __shfl_xor_sync(0xffffffffu, ls1, 2);
        l0 = l0 * alpha0 + ls0;
        l1 = l1 * alpha1 + ls1;

        #pragma unroll
        for (int j = 0; j < 16; j++) {
            oacc[j][0] *= alpha0; oacc[j][1] *= alpha0;
            oacc[j][2] *= alpha1; oacc[j][3] *= alpha1;
        }
        __syncwarp();

        // ---- O += P @ V ----
        #pragma unroll
        for (int kc = 0; kc < 8; kc++) {
            uint32_t a[4];
            const uint32_t* ap = Ps + (qw + r) * LP + kc * 8 + t;
            a[0] = ap[0]; a[1] = ap[8 * LP]; a[2] = ap[4]; a[3] = ap[8 * LP + 4];
            #pragma unroll
            for (int j = 0; j < 16; j++) {
                uint32_t bf[2];
                const uint32_t* vp = Vs + (kc * 8 + t) * LV + 8 * j + r;
                bf[0] = vp[0]; bf[1] = vp[4 * LV];
                MMA_TF32(oacc[j], a, bf);
            }
        }
        __syncthreads();
    }

    // ---- epilogue: normalize + store tf32-rounded [B,T,H*V_D] ----
    const float inv0 = 1.0f / l0;
    const float inv1 = 1.0f / l1;
    const int gr0 = qrow0 + qw + r;
    float* ob = out + ((size_t)b * TT + gr0) * (NH * V_D) + h * V_D;
    #pragma unroll
    for (int j = 0; j < 16; j++) {
        int c = 8 * j + 2 * t;
        *(float2*)(ob + c) =
            make_float2(roundtf(oacc[j][0] * inv0), roundtf(oacc[j][1] * inv0));
        *(float2*)(ob + (size_t)8 * (NH * V_D) + c) =
            make_float2(roundtf(oacc[j][2] * inv1), roundtf(oacc[j][3] * inv1));
    }
}

// ------------------------- launch -------------------------------------------
extern "C" void kernel_launch(void* const* d_in, const int* in_sizes, int n_in,
                              void* d_out, int out_size)
{
    const float* x         = (const float*)d_in[0];
    const float* W_kv_down = (const float*)d_in[1];
    const float* W_k_nope  = (const float*)d_in[2];
    const float* W_k_rope  = (const float*)d_in[3];
    const float* W_v       = (const float*)d_in[4];
    const float* W_q_down  = (const float*)d_in[5];
    const float* W_q_nope  = (const float*)d_in[6];
    const float* W_q_rope  = (const float*)d_in[7];
    const float* W_o       = (const float*)d_in[8];
    float* out = (float*)d_out;

    float *w_down, *w_kv, *w_q, *w_o, *x_r, *cdown, *kvup, *qup, *qcat, *kcat, *attn;
    cudaGetSymbolAddress((void**)&w_down, g_w_down);
    cudaGetSymbolAddress((void**)&w_kv,   g_w_kv);
    cudaGetSymbolAddress((void**)&w_q,    g_w_q);
    cudaGetSymbolAddress((void**)&w_o,    g_w_o);
    cudaGetSymbolAddress((void**)&x_r,    g_x_r);
    cudaGetSymbolAddress((void**)&cdown,  g_cdown);
    cudaGetSymbolAddress((void**)&kvup,   g_kvup);
    cudaGetSymbolAddress((void**)&qup,    g_qup);
    cudaGetSymbolAddress((void**)&qcat,   g_qcat);
    cudaGetSymbolAddress((void**)&kcat,   g_kcat);
    cudaGetSymbolAddress((void**)&attn,   g_attn);

    cudaFuncSetAttribute(gemm_tf32, cudaFuncAttributeMaxDynamicSharedMemorySize,
                         (int)GEMM_SMEM);
    cudaFuncSetAttribute(flash_attn_mma, cudaFuncAttributeMaxDynamicSharedMemorySize,
                         (int)ATTN_SMEM);

    // ---- weight concat + tf32 pre-rounding (float4 granularity) ----
    #define CR(dst, src, rows, cols, dld, doff) \
        copy_round4<<<592, 256>>>((float4*)(dst), (const float4*)(src), \
                                  rows, (cols)/4, (dld)/4, (doff)/4)
    CR(w_down, W_kv_down, DIM, KV_RANK, N_DOWN, 0);
    CR(w_down, W_q_down,  DIM, Q_RANK,  N_DOWN, KV_RANK);
    CR(w_kv,   W_k_nope,  KV_RANK, NKV*NOPE_D, N_KVUP, 0);
    CR(w_kv,   W_k_rope,  KV_RANK, NKV*ROPE_D, N_KVUP, NKV*NOPE_D);
    CR(w_kv,   W_v,       KV_RANK, NKV*V_D,    N_KVUP, NKV*NOPE_D + NKV*ROPE_D);
    CR(w_q,    W_q_nope,  Q_RANK, NH*NOPE_D, N_QUP, 0);
    CR(w_q,    W_q_rope,  Q_RANK, NH*ROPE_D, N_QUP, NH*NOPE_D);
    CR(w_o,    W_o,       NH*V_D, DIM, DIM, 0);
    CR(x_r,    x,         MROWS, DIM, DIM, 0);
    #undef CR

    // ---- fused down projection: [kv_c | q_c] ----
    gemm_tf32<<<dim3(N_DOWN/128, MROWS/128), 256, GEMM_SMEM>>>(
        x_r, DIM, w_down, cdown, N_DOWN, DIM, 1);

    // ---- fused up projections ----
    gemm_tf32<<<dim3(N_KVUP/128, MROWS/128), 256, GEMM_SMEM>>>(
        cdown, N_DOWN, w_kv, kvup, N_KVUP, KV_RANK, 0);
    gemm_tf32<<<dim3(N_QUP/128, MROWS/128), 256, GEMM_SMEM>>>(
        cdown + KV_RANK, N_DOWN, w_q, qup, N_QUP, Q_RANK, 0);

    // ---- RoPE + layout assembly ----
    {
        size_t nq = (size_t)BB * NH * TT * QK_D;
        assemble_q<<<(unsigned)((nq + 255) / 256), 256>>>(
            qup, N_QUP, qup + NH*NOPE_D, N_QUP, qcat);
        size_t nk = (size_t)BB * NKV * TT * QK_D;
        assemble_k<<<(unsigned)((nk + 255) / 256), 256>>>(
            kvup, N_KVUP, kvup + NKV*NOPE_D, N_KVUP, kcat);
    }

    // ---- attention (tensor-core) ----
    flash_attn_mma<<<dim3(TT / 128, BB * NH), 256, ATTN_SMEM>>>(
        qcat, kcat, kvup + NKV*NOPE_D + NKV*ROPE_D, attn);

    // ---- output projection ----
    gemm_tf32<<<dim3(DIM/128, MROWS/128), 256, GEMM_SMEM>>>(
        attn, NH*V_D, w_o, out, DIM, NH*V_D, 0);
}

// round 5
// speedup vs baseline: 3.3809x; 1.3449x over previous
#include <cuda_runtime.h>
#include <math.h>
#include <stdint.h>

// Problem constants
#define BB 2
#define TT 2048
#define DIM 2048
#define NH 16
#define NKV 4
#define NREP 4
#define ROPE_D 64
#define NOPE_D 128
#define V_D 128
#define QK_D 192
#define KV_RANK 512
#define Q_RANK 1536
#define MROWS (BB*TT)   // 4096

// fused widths
#define N_DOWN 2048            // [kv_c(512) | q_c(1536)]
#define N_KVUP 1280            // [k_nope(512) | k_rope(256) | v(512)]
#define N_QUP  3072            // [q_nope(2048) | q_rope(1024)]
#define VOFF   (NKV*NOPE_D + NKV*ROPE_D)   // 768, v offset in kvup

// ------------------------- scratch (static device memory) -------------------
// Weights stored TRANSPOSED: [N][K], tf32-rounded.
__device__ float g_w_down[N_DOWN * DIM];
__device__ float g_w_kv  [N_KVUP * KV_RANK];
__device__ float g_w_q   [N_QUP * Q_RANK];
__device__ float g_w_o   [DIM * (NH*V_D)];
__device__ float g_x_r   [MROWS * DIM];         // tf32-rounded x
__device__ float g_cdown [MROWS * N_DOWN];      // [kv_c | q_c] rounded
__device__ float g_kvup  [MROWS * N_KVUP];
__device__ float g_qup   [MROWS * N_QUP];
__device__ float g_qcat  [BB*NH  * TT * QK_D];  // rounded, pre-scaled
__device__ float g_kcat  [BB*NKV * TT * QK_D];  // rounded
__device__ float g_vt    [BB*NKV * V_D * TT];   // rounded, [b*512+hkv*128+d][t]
__device__ float g_attn  [MROWS * (NH*V_D)];    // rounded

// ------------------------- common PTX helpers -------------------------------
__device__ __forceinline__ uint32_t f2tf32(float x) {
    uint32_t r;
    asm("cvt.rna.tf32.f32 %0, %1;" : "=r"(r) : "f"(x));
    return r;
}
__device__ __forceinline__ float roundtf(float x) {
    return __uint_as_float(f2tf32(x));
}
__device__ __forceinline__ uint32_t s2u(const void* p) {
    return (uint32_t)__cvta_generic_to_shared(p);
}
__device__ __forceinline__ void cp_async16(void* smem, const void* gmem) {
    asm volatile("cp.async.cg.shared.global [%0], [%1], 16;\n"
                 :: "r"(s2u(smem)), "l"(gmem));
}
__device__ __forceinline__ void cp_commit() {
    asm volatile("cp.async.commit_group;\n" ::: "memory");
}
template<int N>
__device__ __forceinline__ void cp_wait() {
    asm volatile("cp.async.wait_group %0;\n" :: "n"(N) : "memory");
}

#define LDMX4(r0, r1, r2, r3, addr) \
    asm volatile("ldmatrix.sync.aligned.m8n8.x4.shared.b16 {%0,%1,%2,%3}, [%4];" \
                 : "=r"(r0), "=r"(r1), "=r"(r2), "=r"(r3) : "r"(addr))

#define MMA_TF32(c, a, b) \
    asm volatile("mma.sync.aligned.m16n8k8.row.col.f32.tf32.tf32.f32 " \
                 "{%0,%1,%2,%3},{%4,%5,%6,%7},{%8,%9},{%0,%1,%2,%3};" \
                 : "+f"((c)[0]), "+f"((c)[1]), "+f"((c)[2]), "+f"((c)[3]) \
                 : "r"((a)[0]), "r"((a)[1]), "r"((a)[2]), "r"((a)[3]), \
                   "r"((b)[0]), "r"((b)[1]))

// ------------------------- prep kernels --------------------------------------
// round + straight copy (for x)
__global__ void copy_round4(float4* __restrict__ dst, const float4* __restrict__ src,
                            int total)
{
    for (int i = blockIdx.x * blockDim.x + threadIdx.x; i < total;
         i += gridDim.x * blockDim.x) {
        float4 v = src[i];
        v.x = roundtf(v.x); v.y = roundtf(v.y);
        v.z = roundtf(v.z); v.w = roundtf(v.w);
        dst[i] = v;
    }
}

// transpose + round: src [R][C] -> dst[(noff+c)*R + r]
__global__ void trans_round(float* __restrict__ dst, const float* __restrict__ src,
                            int R, int C, int noff)
{
    __shared__ float tile[32][33];
    const int c0 = blockIdx.x * 32, r0 = blockIdx.y * 32;
    for (int i = threadIdx.y; i < 32; i += 8)
        tile[i][threadIdx.x] = roundtf(src[(size_t)(r0 + i) * C + c0 + threadIdx.x]);
    __syncthreads();
    for (int i = threadIdx.y; i < 32; i += 8)
        dst[(size_t)(noff + c0 + i) * R + r0 + threadIdx.x] = tile[threadIdx.x][i];
}

// V transpose + round: kvup[row=b*T+t][VOFF + hkv*128 + d] -> vt[(b*512 + hkv*128 + d)*T + t]
__global__ void trans_v(float* __restrict__ dst, const float* __restrict__ src)
{
    __shared__ float tile[32][33];
    const int c0 = blockIdx.x * 32, r0 = blockIdx.y * 32;
    for (int i = threadIdx.y; i < 32; i += 8)
        tile[i][threadIdx.x] =
            roundtf(src[(size_t)(r0 + i) * N_KVUP + VOFF + c0 + threadIdx.x]);
    __syncthreads();
    const int b = r0 >> 11;
    for (int i = threadIdx.y; i < 32; i += 8)
        dst[(size_t)(b * 512 + c0 + i) * TT + (r0 & 2047) + threadIdx.x] =
            tile[threadIdx.x][i];
}

// ------------------------- tf32 tensor-core GEMM ----------------------------
// C[M,N] = A[M,K] @ Bt[N,K]^T; A pitch lda, Bt pitch K. Pre-rounded inputs.
#define LDT 36
#define TSZ (128*LDT)
#define GEMM_SMEM ((4*TSZ)*sizeof(float))

__global__ __launch_bounds__(256, 2) void gemm_tf32(
    const float* __restrict__ A, int lda,
    const float* __restrict__ Bt,
    float* __restrict__ C, int N, int K, int round_c)
{
    extern __shared__ float sm[];
    float* As  = sm;                 // [2][128][LDT]
    float* Bts = sm + 2 * TSZ;       // [2][128][LDT]

    const int tid  = threadIdx.x;
    const int lane = tid & 31;
    const int wid  = tid >> 5;
    const int bx = blockIdx.x, by = blockIdx.y;

    const int m0 = (wid & 1) * 64;
    const int n0 = (wid >> 1) * 32;

    const int rselA = ((lane >> 3) & 1) * 8 + (lane & 7);
    const int cselA = (lane >> 4) * 4;
    const int rselB = ((lane >> 4) & 1) * 8 + (lane & 7);
    const int cselB = ((lane >> 3) & 1) * 4;

    const int l_row = tid >> 1;            // 0..127
    const int l_col = (tid & 1) * 16;      // 0 or 16

    const float* Agb = A  + (size_t)(by * 128 + l_row) * lda + l_col;
    const float* Bgb = Bt + (size_t)(bx * 128 + l_row) * K   + l_col;

    float acc[4][4][4];
    #pragma unroll
    for (int i = 0; i < 4; i++)
        #pragma unroll
        for (int j = 0; j < 4; j++)
            #pragma unroll
            for (int r = 0; r < 4; r++) acc[i][j][r] = 0.f;

    const int nch = K >> 5;

    {
        float* Asb = As  + l_row * LDT + l_col;
        float* Bsb = Bts + l_row * LDT + l_col;
        #pragma unroll
        for (int i = 0; i < 4; i++) cp_async16(Asb + i*4, Agb + i*4);
        #pragma unroll
        for (int i = 0; i < 4; i++) cp_async16(Bsb + i*4, Bgb + i*4);
        cp_commit();
    }

    for (int ch = 0; ch < nch; ch++) {
        if (ch + 1 < nch) {
            const int nb = (ch + 1) & 1;
            const int k0 = (ch + 1) << 5;
            float* Asb = As  + nb * TSZ + l_row * LDT + l_col;
            float* Bsb = Bts + nb * TSZ + l_row * LDT + l_col;
            const float* Ag = Agb + k0;
            const float* Bg = Bgb + k0;
            #pragma unroll
            for (int i = 0; i < 4; i++) cp_async16(Asb + i*4, Ag + i*4);
            #pragma unroll
            for (int i = 0; i < 4; i++) cp_async16(Bsb + i*4, Bg + i*4);
            cp_commit();
            cp_wait<1>();
        } else {
            cp_wait<0>();
        }
        __syncthreads();

        const float* Asb = As  + (ch & 1) * TSZ;
        const float* Bsb = Bts + (ch & 1) * TSZ;

        #pragma unroll
        for (int kk = 0; kk < 4; kk++) {
            uint32_t af[4][4], bf[4][2];
            #pragma unroll
            for (int mi = 0; mi < 4; mi++) {
                LDMX4(af[mi][0], af[mi][1], af[mi][2], af[mi][3],
                      s2u(Asb + (m0 + mi*16 + rselA) * LDT + kk*8 + cselA));
            }
            #pragma unroll
            for (int nip = 0; nip < 2; nip++) {
                LDMX4(bf[2*nip][0], bf[2*nip][1], bf[2*nip+1][0], bf[2*nip+1][1],
                      s2u(Bsb + (n0 + nip*16 + rselB) * LDT + kk*8 + cselB));
            }
            #pragma unroll
            for (int mi = 0; mi < 4; mi++)
                #pragma unroll
                for (int ni = 0; ni < 4; ni++)
                    MMA_TF32(acc[mi][ni], af[mi], bf[ni]);
        }
        __syncthreads();
    }

    const int crow = by * 128 + m0 + (lane >> 2);
    const int ccol = bx * 128 + n0 + (lane & 3) * 2;
    #pragma unroll
    for (int mi = 0; mi < 4; mi++) {
        #pragma unroll
        for (int ni = 0; ni < 4; ni++) {
            const int r = crow + mi * 16;
            const int c = ccol + ni * 8;
            float v0 = acc[mi][ni][0], v1 = acc[mi][ni][1];
            float v2 = acc[mi][ni][2], v3 = acc[mi][ni][3];
            if (round_c) {
                v0 = roundtf(v0); v1 = roundtf(v1);
                v2 = roundtf(v2); v3 = roundtf(v3);
            }
            *(float2*)(C + (size_t)r * N + c) = make_float2(v0, v1);
            *(float2*)(C + (size_t)(r + 8) * N + c) = make_float2(v2, v3);
        }
    }
}

// ------------------------- RoPE + assembly (rounded outputs) -----------------
__device__ __forceinline__ float rope_val(const float* base, size_t rowoff,
                                          int dr, int t)
{
    int j = dr & 31;
    float theta = 1.0f / powf(10000.0f, (float)j * (1.0f / 32.0f));
    float ang = (float)t * theta;
    float c = cosf(ang), s = sinf(ang);
    float x0  = base[rowoff + dr];
    float rot = (dr < 32) ? -base[rowoff + dr + 32] : base[rowoff + dr - 32];
    return x0 * c + rot * s;
}

__global__ void assemble_q(const float* __restrict__ qn, int qnld,
                           const float* __restrict__ qr, int qrld,
                           float* __restrict__ qcat)
{
    size_t idx = (size_t)blockIdx.x * blockDim.x + threadIdx.x;
    const size_t total = (size_t)BB * NH * TT * QK_D;
    if (idx >= total) return;
    int d = (int)(idx % QK_D);
    size_t rem = idx / QK_D;
    int t = (int)(rem % TT); rem /= TT;
    int h = (int)(rem % NH);
    int b = (int)(rem / NH);
    size_t row = (size_t)b * TT + t;
    const float scale = rsqrtf((float)QK_D);
    float val;
    if (d < NOPE_D) val = qn[row * qnld + h * NOPE_D + d];
    else            val = rope_val(qr, row * qrld + h * ROPE_D, d - NOPE_D, t);
    qcat[idx] = roundtf(val * scale);
}

__global__ void assemble_k(const float* __restrict__ kn, int knld,
                           const float* __restrict__ kr, int krld,
                           float* __restrict__ kcat)
{
    size_t idx = (size_t)blockIdx.x * blockDim.x + threadIdx.x;
    const size_t total = (size_t)BB * NKV * TT * QK_D;
    if (idx >= total) return;
    int d = (int)(idx % QK_D);
    size_t rem = idx / QK_D;
    int t = (int)(rem % TT); rem /= TT;
    int h = (int)(rem % NKV);
    int b = (int)(rem / NKV);
    size_t row = (size_t)b * TT + t;
    float val;
    if (d < NOPE_D) val = kn[row * knld + h * NOPE_D + d];
    else            val = rope_val(kr, row * krld + h * ROPE_D, d - NOPE_D, t);
    kcat[idx] = roundtf(val);
}

// ------------------------- flash attention (tf32 mma + ldmatrix) ------------
#define LQ 196
#define LK 196
#define LVT 68
#define LP 68
#define QS_SZ (128*LQ)
#define KS_SZ (64*LK)
#define VTS_SZ (128*LVT)
#define PS_SZ (128*LP)
#define ATTN_SMEM ((QS_SZ + KS_SZ + VTS_SZ + PS_SZ) * sizeof(float))

__global__ __launch_bounds__(256) void flash_attn_mma(
    const float* __restrict__ q, const float* __restrict__ k,
    const float* __restrict__ vt, float* __restrict__ out)
{
    extern __shared__ float sf[];
    float* Qs  = sf;
    float* Ks  = sf + QS_SZ;
    float* Vts = Ks + KS_SZ;
    float* Ps  = Vts + VTS_SZ;

    const int qi   = blockIdx.x;
    const int head = blockIdx.y;
    const int b = head / NH, h = head % NH;
    const int hkv = h / NREP;
    const int tid = threadIdx.x;
    const int lane = tid & 31, wid = tid >> 5;
    const int r = lane >> 2, t = lane & 3;
    const int qw = wid * 16;
    const int qrow0 = qi * 128;

    const int rselA = ((lane >> 3) & 1) * 8 + (lane & 7);
    const int cselA = (lane >> 4) * 4;
    const int rselB = ((lane >> 4) & 1) * 8 + (lane & 7);
    const int cselB = ((lane >> 3) & 1) * 4;

    const float* qbase = q + ((size_t)head * TT + qrow0) * QK_D;
    const float* kbase = k + ((size_t)(b * NKV + hkv) * TT) * QK_D;
    const float* vtbase = vt + (size_t)(b * 512 + hkv * 128) * TT;

    // Q -> smem (async)
    for (int i = tid; i < 128 * 48; i += 256) {
        int rr = i / 48, c4 = i % 48;
        cp_async16(Qs + rr * LQ + c4 * 4, qbase + (size_t)rr * QK_D + c4 * 4);
    }
    cp_commit();

    float m0 = -1e30f, m1 = -1e30f, l0 = 0.f, l1 = 0.f;
    float oacc[16][4];
    #pragma unroll
    for (int j = 0; j < 16; j++)
        #pragma unroll
        for (int c = 0; c < 4; c++) oacc[j][c] = 0.f;

    const int niter = 2 * qi + 2;
    for (int jt = 0; jt < niter; jt++) {
        const int krow0 = jt * 64;

        for (int i = tid; i < 64 * 48; i += 256) {
            int rr = i / 48, c4 = i % 48;
            cp_async16(Ks + rr * LK + c4 * 4,
                       kbase + (size_t)(krow0 + rr) * QK_D + c4 * 4);
        }
        for (int i = tid; i < 128 * 16; i += 256) {
            int rr = i >> 4, c4 = i & 15;
            cp_async16(Vts + rr * LVT + c4 * 4,
                       vtbase + (size_t)rr * TT + krow0 + c4 * 4);
        }
        cp_commit();
        cp_wait<0>();
        __syncthreads();

        // ---- S = Q @ K^T ----
        float sacc[8][4];
        #pragma unroll
        for (int j = 0; j < 8; j++)
            #pragma unroll
            for (int c = 0; c < 4; c++) sacc[j][c] = 0.f;

        #pragma unroll 2
        for (int kc = 0; kc < 24; kc++) {
            uint32_t a[4];
            LDMX4(a[0], a[1], a[2], a[3],
                  s2u(Qs + (qw + rselA) * LQ + kc*8 + cselA));
            #pragma unroll
            for (int jp = 0; jp < 4; jp++) {
                uint32_t b0[2], b1[2];
                LDMX4(b0[0], b0[1], b1[0], b1[1],
                      s2u(Ks + (jp*16 + rselB) * LK + kc*8 + cselB));
                MMA_TF32(sacc[2*jp],   a, b0);
                MMA_TF32(sacc[2*jp+1], a, b1);
            }
        }

        // ---- mask + online softmax ----
        const int gr0 = qrow0 + qw + r;
        const bool need_mask = (jt >= 2 * qi);
        float mx0 = m0, mx1 = m1;
        #pragma unroll
        for (int j = 0; j < 8; j++) {
            if (need_mask) {
                int gc = krow0 + 8 * j + 2 * t;
                if (gc     > gr0)     sacc[j][0] = -1e30f;
                if (gc + 1 > gr0)     sacc[j][1] = -1e30f;
                if (gc     > gr0 + 8) sacc[j][2] = -1e30f;
                if (gc + 1 > gr0 + 8) sacc[j][3] = -1e30f;
            }
            mx0 = fmaxf(mx0, fmaxf(sacc[j][0], sacc[j][1]));
            mx1 = fmaxf(mx1, fmaxf(sacc[j][2], sacc[j][3]));
        }
        mx0 = fmaxf(mx0, __shfl_xor_sync(0xffffffffu, mx0, 1));
        mx0 = fmaxf(mx0, __shfl_xor_sync(0xffffffffu, mx0, 2));
        mx1 = fmaxf(mx1, __shfl_xor_sync(0xffffffffu, mx1, 1));
        mx1 = fmaxf(mx1, __shfl_xor_sync(0xffffffffu, mx1, 2));

        float alpha0 = __expf(m0 - mx0);
        float alpha1 = __expf(m1 - mx1);
        m0 = mx0; m1 = mx1;

        float ls0 = 0.f, ls1 = 0.f;
        float* pp = Ps + (qw + r) * LP;
        #pragma unroll
        for (int j = 0; j < 8; j++) {
            float p0 = __expf(sacc[j][0] - mx0);
            float p1 = __expf(sacc[j][1] - mx0);
            float p2 = __expf(sacc[j][2] - mx1);
            float p3 = __expf(sacc[j][3] - mx1);
            ls0 += p0 + p1; ls1 += p2 + p3;
            pp[8 * j + 2 * t]              = roundtf(p0);
            pp[8 * j + 2 * t + 1]          = roundtf(p1);
            pp[8 * LP + 8 * j + 2 * t]     = roundtf(p2);
            pp[8 * LP + 8 * j + 2 * t + 1] = roundtf(p3);
        }
        ls0 += __shfl_xor_sync(0xffffffffu, ls0, 1);
        ls0 += __shfl_xor_sync(0xffffffffu, ls0, 2);
        ls1 += __shfl_xor_sync(0xffffffffu, ls1, 1);
        ls1 += __shfl_xor_sync(0xffffffffu, ls1, 2);
        l0 = l0 * alpha0 + ls0;
        l1 = l1 * alpha1 + ls1;

        #pragma unroll
        for (int j = 0; j < 16; j++) {
            oacc[j][0] *= alpha0; oacc[j][1] *= alpha0;
            oacc[j][2] *= alpha1; oacc[j][3] *= alpha1;
        }
        __syncwarp();

        // ---- O += P @ V (V^t fragments via ldmatrix) ----
        #pragma unroll
        for (int kc = 0; kc < 8; kc++) {
            uint32_t a[4];
            LDMX4(a[0], a[1], a[2], a[3],
                  s2u(Ps + (qw + rselA) * LP + kc*8 + cselA));
            #pragma unroll
            for (int jp = 0; jp < 8; jp++) {
                uint32_t b0[2], b1[2];
                LDMX4(b0[0], b0[1], b1[0], b1[1],
                      s2u(Vts + (jp*16 + rselB) * LVT + kc*8 + cselB));
                MMA_TF32(oacc[2*jp],   a, b0);
                MMA_TF32(oacc[2*jp+1], a, b1);
            }
        }
        __syncthreads();
    }

    // ---- epilogue: normalize + store rounded [B,T,H*V_D] ----
    const float inv0 = 1.0f / l0;
    const float inv1 = 1.0f / l1;
    const int gr0 = qrow0 + qw + r;
    float* ob = out + ((size_t)b * TT + gr0) * (NH * V_D) + h * V_D;
    #pragma unroll
    for (int j = 0; j < 16; j++) {
        int c = 8 * j + 2 * t;
        *(float2*)(ob + c) =
            make_float2(roundtf(oacc[j][0] * inv0), roundtf(oacc[j][1] * inv0));
        *(float2*)(ob + (size_t)8 * (NH * V_D) + c) =
            make_float2(roundtf(oacc[j][2] * inv1), roundtf(oacc[j][3] * inv1));
    }
}

// ------------------------- launch -------------------------------------------
extern "C" void kernel_launch(void* const* d_in, const int* in_sizes, int n_in,
                              void* d_out, int out_size)
{
    const float* x         = (const float*)d_in[0];
    const float* W_kv_down = (const float*)d_in[1];
    const float* W_k_nope  = (const float*)d_in[2];
    const float* W_k_rope  = (const float*)d_in[3];
    const float* W_v       = (const float*)d_in[4];
    const float* W_q_down  = (const float*)d_in[5];
    const float* W_q_nope  = (const float*)d_in[6];
    const float* W_q_rope  = (const float*)d_in[7];
    const float* W_o       = (const float*)d_in[8];
    float* out = (float*)d_out;

    float *w_down, *w_kv, *w_q, *w_o, *x_r, *cdown, *kvup, *qup, *qcat, *kcat, *vt, *attn;
    cudaGetSymbolAddress((void**)&w_down, g_w_down);
    cudaGetSymbolAddress((void**)&w_kv,   g_w_kv);
    cudaGetSymbolAddress((void**)&w_q,    g_w_q);
    cudaGetSymbolAddress((void**)&w_o,    g_w_o);
    cudaGetSymbolAddress((void**)&x_r,    g_x_r);
    cudaGetSymbolAddress((void**)&cdown,  g_cdown);
    cudaGetSymbolAddress((void**)&kvup,   g_kvup);
    cudaGetSymbolAddress((void**)&qup,    g_qup);
    cudaGetSymbolAddress((void**)&qcat,   g_qcat);
    cudaGetSymbolAddress((void**)&kcat,   g_kcat);
    cudaGetSymbolAddress((void**)&vt,     g_vt);
    cudaGetSymbolAddress((void**)&attn,   g_attn);

    cudaFuncSetAttribute(gemm_tf32, cudaFuncAttributeMaxDynamicSharedMemorySize,
                         (int)GEMM_SMEM);
    cudaFuncSetAttribute(flash_attn_mma, cudaFuncAttributeMaxDynamicSharedMemorySize,
                         (int)ATTN_SMEM);

    const dim3 tb(32, 8);
    // ---- weight transpose + round (concat into [N][K]) ----
    trans_round<<<dim3(512/32, 2048/32),  tb>>>(w_down, W_kv_down, DIM, KV_RANK, 0);
    trans_round<<<dim3(1536/32, 2048/32), tb>>>(w_down, W_q_down,  DIM, Q_RANK,  KV_RANK);
    trans_round<<<dim3(512/32, 512/32),   tb>>>(w_kv, W_k_nope, KV_RANK, NKV*NOPE_D, 0);
    trans_round<<<dim3(256/32, 512/32),   tb>>>(w_kv, W_k_rope, KV_RANK, NKV*ROPE_D, NKV*NOPE_D);
    trans_round<<<dim3(512/32, 512/32),   tb>>>(w_kv, W_v,      KV_RANK, NKV*V_D,    VOFF);
    trans_round<<<dim3(2048/32, 1536/32), tb>>>(w_q, W_q_nope, Q_RANK, NH*NOPE_D, 0);
    trans_round<<<dim3(1024/32, 1536/32), tb>>>(w_q, W_q_rope, Q_RANK, NH*ROPE_D, NH*NOPE_D);
    trans_round<<<dim3(2048/32, 2048/32), tb>>>(w_o, W_o, NH*V_D, DIM, 0);
    copy_round4<<<592, 256>>>((float4*)x_r, (const float4*)x, MROWS * DIM / 4);

    // ---- fused down projection: [kv_c | q_c] ----
    gemm_tf32<<<dim3(N_DOWN/128, MROWS/128), 256, GEMM_SMEM>>>(
        x_r, DIM, w_down, cdown, N_DOWN, DIM, 1);

    // ---- fused up projections ----
    gemm_tf32<<<dim3(N_KVUP/128, MROWS/128), 256, GEMM_SMEM>>>(
        cdown, N_DOWN, w_kv, kvup, N_KVUP, KV_RANK, 0);
    gemm_tf32<<<dim3(N_QUP/128, MROWS/128), 256, GEMM_SMEM>>>(
        cdown + KV_RANK, N_DOWN, w_q, qup, N_QUP, Q_RANK, 0);

    // ---- RoPE + layout assembly + V transpose ----
    {
        size_t nq = (size_t)BB * NH * TT * QK_D;
        assemble_q<<<(unsigned)((nq + 255) / 256), 256>>>(
            qup, N_QUP, qup + NH*NOPE_D, N_QUP, qcat);
        size_t nk = (size_t)BB * NKV * TT * QK_D;
        assemble_k<<<(unsigned)((nk + 255) / 256), 256>>>(
            kvup, N_KVUP, kvup + NKV*NOPE_D, N_KVUP, kcat);
        trans_v<<<dim3(512/32, MROWS/32), tb>>>(vt, kvup);
    }

    // ---- attention ----
    flash_attn_mma<<<dim3(TT / 128, BB * NH), 256, ATTN_SMEM>>>(
        qcat, kcat, vt, attn);

    // ---- output projection ----
    gemm_tf32<<<dim3(DIM/128, MROWS/128), 256, GEMM_SMEM>>>(
        attn, NH*V_D, w_o, out, DIM, NH*V_D, 0);
}

// round 7
// speedup vs baseline: 3.8912x; 1.1509x over previous
#include <cuda_runtime.h>
#include <math.h>
#include <stdint.h>

// Problem constants
#define BB 2
#define TT 2048
#define DIM 2048
#define NH 16
#define NKV 4
#define NREP 4
#define ROPE_D 64
#define NOPE_D 128
#define V_D 128
#define QK_D 192
#define KV_RANK 512
#define Q_RANK 1536
#define MROWS (BB*TT)   // 4096

// fused widths
#define N_DOWN 2048            // [kv_c(512) | q_c(1536)]
#define N_KVUP 1280            // [k_nope(512) | k_rope(256) | v(512)]
#define N_QUP  3072            // [q_nope(2048) | q_rope(1024)]
#define VOFF   (NKV*NOPE_D + NKV*ROPE_D)   // 768

// ------------------------- scratch (static device memory) -------------------
__device__ float g_w_down[N_DOWN * DIM];        // transposed [N][K], tf32-rounded
__device__ float g_w_kv  [N_KVUP * KV_RANK];
__device__ float g_w_q   [N_QUP * Q_RANK];
__device__ float g_w_o   [DIM * (NH*V_D)];
__device__ float g_x_r   [MROWS * DIM];
__device__ float g_cdown [MROWS * N_DOWN];
__device__ float g_kvup  [MROWS * N_KVUP];
__device__ float g_qup   [MROWS * N_QUP];
__device__ float g_qcat  [BB*NH  * TT * QK_D];
__device__ float g_kcat  [BB*NKV * TT * QK_D];
__device__ float g_vt    [BB*NKV * V_D * TT];
__device__ float g_attn  [MROWS * (NH*V_D)];
__device__ float g_ropec [TT * ROPE_D];
__device__ float g_ropes [TT * ROPE_D];

// ------------------------- common PTX helpers -------------------------------
__device__ __forceinline__ uint32_t f2tf32(float x) {
    uint32_t r;
    asm("cvt.rna.tf32.f32 %0, %1;" : "=r"(r) : "f"(x));
    return r;
}
__device__ __forceinline__ float roundtf(float x) {
    return __uint_as_float(f2tf32(x));
}
__device__ __forceinline__ uint32_t s2u(const void* p) {
    return (uint32_t)__cvta_generic_to_shared(p);
}
__device__ __forceinline__ void cp_async16(void* smem, const void* gmem) {
    asm volatile("cp.async.cg.shared.global [%0], [%1], 16;\n"
                 :: "r"(s2u(smem)), "l"(gmem));
}
__device__ __forceinline__ void cp_commit() {
    asm volatile("cp.async.commit_group;\n" ::: "memory");
}
template<int N>
__device__ __forceinline__ void cp_wait() {
    asm volatile("cp.async.wait_group %0;\n" :: "n"(N) : "memory");
}

#define LDMX4(r0, r1, r2, r3, addr) \
    asm volatile("ldmatrix.sync.aligned.m8n8.x4.shared.b16 {%0,%1,%2,%3}, [%4];" \
                 : "=r"(r0), "=r"(r1), "=r"(r2), "=r"(r3) : "r"(addr))

#define MMA_TF32(c, a, b) \
    asm volatile("mma.sync.aligned.m16n8k8.row.col.f32.tf32.tf32.f32 " \
                 "{%0,%1,%2,%3},{%4,%5,%6,%7},{%8,%9},{%0,%1,%2,%3};" \
                 : "+f"((c)[0]), "+f"((c)[1]), "+f"((c)[2]), "+f"((c)[3]) \
                 : "r"((a)[0]), "r"((a)[1]), "r"((a)[2]), "r"((a)[3]), \
                   "r"((b)[0]), "r"((b)[1]))

// ------------------------- prep kernels --------------------------------------
__global__ void copy_round4(float4* __restrict__ dst, const float4* __restrict__ src,
                            int total)
{
    for (int i = blockIdx.x * blockDim.x + threadIdx.x; i < total;
         i += gridDim.x * blockDim.x) {
        float4 v = src[i];
        v.x = roundtf(v.x); v.y = roundtf(v.y);
        v.z = roundtf(v.z); v.w = roundtf(v.w);
        dst[i] = v;
    }
}

// merged transpose+round: 8 jobs in one launch
struct TJobs {
    const float* src[8];
    float* dst[8];
    int R[8], C[8], noff[8], start[8];
    int njobs;
};

__global__ void trans_round_multi(TJobs jobs)
{
    __shared__ float tile[32][33];
    const int bid = blockIdx.x;
    int jj = 0;
    #pragma unroll
    for (int k = 1; k < 8; k++)
        if (k < jobs.njobs && bid >= jobs.start[k]) jj = k;
    const int local = bid - jobs.start[jj];
    const int C = jobs.C[jj], R = jobs.R[jj], noff = jobs.noff[jj];
    const int tx = C >> 5;
    const int c0 = (local % tx) * 32;
    const int r0 = (local / tx) * 32;
    const float* src = jobs.src[jj];
    float* dst = jobs.dst[jj];

    for (int i = threadIdx.y; i < 32; i += 8)
        tile[i][threadIdx.x] = roundtf(src[(size_t)(r0 + i) * C + c0 + threadIdx.x]);
    __syncthreads();
    for (int i = threadIdx.y; i < 32; i += 8)
        dst[(size_t)(noff + c0 + i) * R + r0 + threadIdx.x] = tile[threadIdx.x][i];
}

// rope cos/sin table: [t][dr], dr in [0,64)
__global__ void rope_table(float* __restrict__ rc, float* __restrict__ rs)
{
    int idx = blockIdx.x * blockDim.x + threadIdx.x;
    if (idx >= TT * ROPE_D) return;
    int t = idx >> 6, dr = idx & 63;
    int j = dr & 31;
    float theta = exp2f(-0.4152410118609203f * (float)j);  // 10000^(-j/32)
    float ang = (float)t * theta;
    rc[idx] = cosf(ang);
    rs[idx] = sinf(ang);
}

// V transpose + round
__global__ void trans_v(float* __restrict__ dst, const float* __restrict__ src)
{
    __shared__ float tile[32][33];
    const int c0 = blockIdx.x * 32, r0 = blockIdx.y * 32;
    for (int i = threadIdx.y; i < 32; i += 8)
        tile[i][threadIdx.x] =
            roundtf(src[(size_t)(r0 + i) * N_KVUP + VOFF + c0 + threadIdx.x]);
    __syncthreads();
    const int b = r0 >> 11;
    for (int i = threadIdx.y; i < 32; i += 8)
        dst[(size_t)(b * 512 + c0 + i) * TT + (r0 & 2047) + threadIdx.x] =
            tile[threadIdx.x][i];
}

// ------------------------- tf32 tensor-core GEMM (mma.sync) -----------------
// C[M,N] = A[M,K] @ Bt[N,K]^T; 3-stage cp.async ring, one barrier per chunk.
#define LDT 36
#define TSZ (128*LDT)                       // floats per operand per stage
#define GST3 3
#define G3_SMEM (GST3 * 2 * TSZ * sizeof(float))   // 110592 B

__global__ __launch_bounds__(256, 2) void gemm_tf32(
    const float* __restrict__ A, int lda,
    const float* __restrict__ Bt,
    float* __restrict__ C, int N, int K, int round_c)
{
    extern __shared__ float sm[];

    const int tid  = threadIdx.x;
    const int lane = tid & 31;
    const int wid  = tid >> 5;
    const int bx = blockIdx.x, by = blockIdx.y;

    const int m0 = (wid & 1) * 64;
    const int n0 = (wid >> 1) * 32;

    const int rselA = ((lane >> 3) & 1) * 8 + (lane & 7);
    const int cselA = (lane >> 4) * 4;
    const int rselB = ((lane >> 4) & 1) * 8 + (lane & 7);
    const int cselB = ((lane >> 3) & 1) * 4;

    const int l_row = tid >> 1;
    const int l_col = (tid & 1) * 16;

    const float* Agb = A  + (size_t)(by * 128 + l_row) * lda + l_col;
    const float* Bgb = Bt + (size_t)(bx * 128 + l_row) * K   + l_col;

    float acc[4][4][4];
    #pragma unroll
    for (int i = 0; i < 4; i++)
        #pragma unroll
        for (int j = 0; j < 4; j++)
            #pragma unroll
            for (int r = 0; r < 4; r++) acc[i][j][r] = 0.f;

    const int nch = K >> 5;

    // prologue: stages 0,1
    #pragma unroll
    for (int p = 0; p < 2; p++) {
        float* Asb = sm + p * 2 * TSZ + l_row * LDT + l_col;
        float* Bsb = Asb + TSZ;
        const float* Ag = Agb + p * 32;
        const float* Bg = Bgb + p * 32;
        #pragma unroll
        for (int i = 0; i < 4; i++) cp_async16(Asb + i*4, Ag + i*4);
        #pragma unroll
        for (int i = 0; i < 4; i++) cp_async16(Bsb + i*4, Bg + i*4);
        cp_commit();
    }

    int s = 0, s2 = 2;
    for (int ch = 0; ch < nch; ch++) {
        cp_wait<1>();
        __syncthreads();

        // prefetch chunk ch+2 into stage s2 (freed at top barrier)
        if (ch + 2 < nch) {
            const int k0 = (ch + 2) << 5;
            float* Asb = sm + s2 * 2 * TSZ + l_row * LDT + l_col;
            float* Bsb = Asb + TSZ;
            const float* Ag = Agb + k0;
            const float* Bg = Bgb + k0;
            #pragma unroll
            for (int i = 0; i < 4; i++) cp_async16(Asb + i*4, Ag + i*4);
            #pragma unroll
            for (int i = 0; i < 4; i++) cp_async16(Bsb + i*4, Bg + i*4);
        }
        cp_commit();   // (possibly empty) keeps group arithmetic uniform

        const float* Asb = sm + s * 2 * TSZ;
        const float* Bsb = Asb + TSZ;

        #pragma unroll
        for (int kk = 0; kk < 4; kk++) {
            uint32_t af[4][4], bf[4][2];
            #pragma unroll
            for (int mi = 0; mi < 4; mi++) {
                LDMX4(af[mi][0], af[mi][1], af[mi][2], af[mi][3],
                      s2u(Asb + (m0 + mi*16 + rselA) * LDT + kk*8 + cselA));
            }
            #pragma unroll
            for (int nip = 0; nip < 2; nip++) {
                LDMX4(bf[2*nip][0], bf[2*nip][1], bf[2*nip+1][0], bf[2*nip+1][1],
                      s2u(Bsb + (n0 + nip*16 + rselB) * LDT + kk*8 + cselB));
            }
            #pragma unroll
            for (int mi = 0; mi < 4; mi++)
                #pragma unroll
                for (int ni = 0; ni < 4; ni++)
                    MMA_TF32(acc[mi][ni], af[mi], bf[ni]);
        }
        s  = (s  == GST3-1) ? 0 : s  + 1;
        s2 = (s2 == GST3-1) ? 0 : s2 + 1;
    }

    const int crow = by * 128 + m0 + (lane >> 2);
    const int ccol = bx * 128 + n0 + (lane & 3) * 2;
    #pragma unroll
    for (int mi = 0; mi < 4; mi++) {
        #pragma unroll
        for (int ni = 0; ni < 4; ni++) {
            const int r = crow + mi * 16;
            const int c = ccol + ni * 8;
            float v0 = acc[mi][ni][0], v1 = acc[mi][ni][1];
            float v2 = acc[mi][ni][2], v3 = acc[mi][ni][3];
            if (round_c) {
                v0 = roundtf(v0); v1 = roundtf(v1);
                v2 = roundtf(v2); v3 = roundtf(v3);
            }
            *(float2*)(C + (size_t)r * N + c) = make_float2(v0, v1);
            *(float2*)(C + (size_t)(r + 8) * N + c) = make_float2(v2, v3);
        }
    }
}

// ------------------------- RoPE + assembly (table-based) ---------------------
__global__ void assemble_q(const float* __restrict__ qn, int qnld,
                           const float* __restrict__ qr, int qrld,
                           const float* __restrict__ rc,
                           const float* __restrict__ rs,
                           float* __restrict__ qcat)
{
    size_t idx = (size_t)blockIdx.x * blockDim.x + threadIdx.x;
    const size_t total = (size_t)BB * NH * TT * QK_D;
    if (idx >= total) return;
    int d = (int)(idx % QK_D);
    size_t rem = idx / QK_D;
    int t = (int)(rem % TT); rem /= TT;
    int h = (int)(rem % NH);
    int b = (int)(rem / NH);
    size_t row = (size_t)b * TT + t;
    const float scale = rsqrtf((float)QK_D);
    float val;
    if (d < NOPE_D) {
        val = qn[row * qnld + h * NOPE_D + d];
    } else {
        int dr = d - NOPE_D;
        size_t ro = row * qrld + h * ROPE_D;
        float x0  = qr[ro + dr];
        float rot = (dr < 32) ? -qr[ro + dr + 32] : qr[ro + dr - 32];
        val = x0 * rc[t * ROPE_D + dr] + rot * rs[t * ROPE_D + dr];
    }
    qcat[idx] = roundtf(val * scale);
}

__global__ void assemble_k(const float* __restrict__ kn, int knld,
                           const float* __restrict__ kr, int krld,
                           const float* __restrict__ rc,
                           const float* __restrict__ rs,
                           float* __restrict__ kcat)
{
    size_t idx = (size_t)blockIdx.x * blockDim.x + threadIdx.x;
    const size_t total = (size_t)BB * NKV * TT * QK_D;
    if (idx >= total) return;
    int d = (int)(idx % QK_D);
    size_t rem = idx / QK_D;
    int t = (int)(rem % TT); rem /= TT;
    int h = (int)(rem % NKV);
    int b = (int)(rem / NKV);
    size_t row = (size_t)b * TT + t;
    float val;
    if (d < NOPE_D) {
        val = kn[row * knld + h * NOPE_D + d];
    } else {
        int dr = d - NOPE_D;
        size_t ro = row * krld + h * ROPE_D;
        float x0  = kr[ro + dr];
        float rot = (dr < 32) ? -kr[ro + dr + 32] : kr[ro + dr - 32];
        val = x0 * rc[t * ROPE_D + dr] + rot * rs[t * ROPE_D + dr];
    }
    kcat[idx] = roundtf(val);
}

// ------------------------- flash attention (tf32 mma + ldmatrix) ------------
// Single-buffered software pipeline: K_{jt+1} issued during PV_jt,
// V_{jt+1} issued after end-of-iter barrier (lands during S_{jt+1}).
#define LQ 196
#define LK 196
#define LVT 68
#define LP 68
#define QS_SZ (128*LQ)
#define KS_SZ (64*LK)
#define VTS_SZ (128*LVT)
#define PS_SZ (128*LP)
#define ATTN_SMEM ((QS_SZ + KS_SZ + VTS_SZ + PS_SZ) * sizeof(float))

__global__ __launch_bounds__(256) void flash_attn_mma(
    const float* __restrict__ q, const float* __restrict__ k,
    const float* __restrict__ vt, float* __restrict__ out)
{
    extern __shared__ float sf[];
    float* Qs  = sf;
    float* Ks  = sf + QS_SZ;
    float* Vts = Ks + KS_SZ;
    float* Ps  = Vts + VTS_SZ;

    const int bid  = blockIdx.x;
    const int qi   = (TT/128 - 1) - (bid >> 5);   // big tiles scheduled first
    const int head = bid & 31;
    const int b = head / NH, h = head % NH;
    const int hkv = h / NREP;
    const int tid = threadIdx.x;
    const int lane = tid & 31, wid = tid >> 5;
    const int r = lane >> 2, t = lane & 3;
    const int qw = wid * 16;
    const int qrow0 = qi * 128;

    const int rselA = ((lane >> 3) & 1) * 8 + (lane & 7);
    const int cselA = (lane >> 4) * 4;
    const int rselB = ((lane >> 4) & 1) * 8 + (lane & 7);
    const int cselB = ((lane >> 3) & 1) * 4;

    const float* qbase = q + ((size_t)head * TT + qrow0) * QK_D;
    const float* kbase = k + ((size_t)(b * NKV + hkv) * TT) * QK_D;
    const float* vtbase = vt + (size_t)(b * 512 + hkv * 128) * TT;

    // prefetch: Q (group), K0 (group), V0 (group)
    for (int i = tid; i < 128 * 48; i += 256) {
        int rr = i / 48, c4 = i % 48;
        cp_async16(Qs + rr * LQ + c4 * 4, qbase + (size_t)rr * QK_D + c4 * 4);
    }
    cp_commit();
    for (int i = tid; i < 64 * 48; i += 256) {
        int rr = i / 48, c4 = i % 48;
        cp_async16(Ks + rr * LK + c4 * 4, kbase + (size_t)rr * QK_D + c4 * 4);
    }
    cp_commit();
    for (int i = tid; i < 128 * 16; i += 256) {
        int rr = i >> 4, c4 = i & 15;
        cp_async16(Vts + rr * LVT + c4 * 4, vtbase + (size_t)rr * TT + c4 * 4);
    }
    cp_commit();

    float m0 = -1e30f, m1 = -1e30f, l0 = 0.f, l1 = 0.f;
    float oacc[16][4];
    #pragma unroll
    for (int j = 0; j < 16; j++)
        #pragma unroll
        for (int c = 0; c < 4; c++) oacc[j][c] = 0.f;

    const int niter = 2 * qi + 2;
    for (int jt = 0; jt < niter; jt++) {
        const int krow0 = jt * 64;

        cp_wait<1>();          // Q + K_jt complete (V_jt may be in flight)
        __syncthreads();

        // ---- S = Q @ K^T ----
        float sacc[8][4];
        #pragma unroll
        for (int j = 0; j < 8; j++)
            #pragma unroll
            for (int c = 0; c < 4; c++) sacc[j][c] = 0.f;

        #pragma unroll 2
        for (int kc = 0; kc < 24; kc++) {
            uint32_t a[4];
            LDMX4(a[0], a[1], a[2], a[3],
                  s2u(Qs + (qw + rselA) * LQ + kc*8 + cselA));
            #pragma unroll
            for (int jp = 0; jp < 4; jp++) {
                uint32_t b0[2], b1[2];
                LDMX4(b0[0], b0[1], b1[0], b1[1],
                      s2u(Ks + (jp*16 + rselB) * LK + kc*8 + cselB));
                MMA_TF32(sacc[2*jp],   a, b0);
                MMA_TF32(sacc[2*jp+1], a, b1);
            }
        }

        // ---- mask + online softmax ----
        const int gr0 = qrow0 + qw + r;
        const bool need_mask = (jt >= 2 * qi);
        float mx0 = m0, mx1 = m1;
        #pragma unroll
        for (int j = 0; j < 8; j++) {
            if (need_mask) {
                int gc = krow0 + 8 * j + 2 * t;
                if (gc     > gr0)     sacc[j][0] = -1e30f;
                if (gc + 1 > gr0)     sacc[j][1] = -1e30f;
                if (gc     > gr0 + 8) sacc[j][2] = -1e30f;
                if (gc + 1 > gr0 + 8) sacc[j][3] = -1e30f;
            }
            mx0 = fmaxf(mx0, fmaxf(sacc[j][0], sacc[j][1]));
            mx1 = fmaxf(mx1, fmaxf(sacc[j][2], sacc[j][3]));
        }
        mx0 = fmaxf(mx0, __shfl_xor_sync(0xffffffffu, mx0, 1));
        mx0 = fmaxf(mx0, __shfl_xor_sync(0xffffffffu, mx0, 2));
        mx1 = fmaxf(mx1, __shfl_xor_sync(0xffffffffu, mx1, 1));
        mx1 = fmaxf(mx1, __shfl_xor_sync(0xffffffffu, mx1, 2));

        float alpha0 = __expf(m0 - mx0);
        float alpha1 = __expf(m1 - mx1);
        m0 = mx0; m1 = mx1;

        float ls0 = 0.f, ls1 = 0.f;
        float* pp = Ps + (qw + r) * LP;
        #pragma unroll
        for (int j = 0; j < 8; j++) {
            float p0 = __expf(sacc[j][0] - mx0);
            float p1 = __expf(sacc[j][1] - mx0);
            float p2 = __expf(sacc[j][2] - mx1);
            float p3 = __expf(sacc[j][3] - mx1);
            ls0 += p0 + p1; ls1 += p2 + p3;
            pp[8 * j + 2 * t]              = roundtf(p0);
            pp[8 * j + 2 * t + 1]          = roundtf(p1);
            pp[8 * LP + 8 * j + 2 * t]     = roundtf(p2);
            pp[8 * LP + 8 * j + 2 * t + 1] = roundtf(p3);
        }
        ls0 += __shfl_xor_sync(0xffffffffu, ls0, 1);
        ls0 += __shfl_xor_sync(0xffffffffu, ls0, 2);
        ls1 += __shfl_xor_sync(0xffffffffu, ls1, 1);
        ls1 += __shfl_xor_sync(0xffffffffu, ls1, 2);
        l0 = l0 * alpha0 + ls0;
        l1 = l1 * alpha1 + ls1;

        #pragma unroll
        for (int j = 0; j < 16; j++) {
            oacc[j][0] *= alpha0; oacc[j][1] *= alpha0;
            oacc[j][2] *= alpha1; oacc[j][3] *= alpha1;
        }

        cp_wait<0>();          // V_jt complete; all threads done reading Ks
        __syncthreads();

        // issue K_{jt+1} now — PV does not touch Ks
        if (jt + 1 < niter) {
            const int kn0 = (jt + 1) * 64;
            for (int i = tid; i < 64 * 48; i += 256) {
                int rr = i / 48, c4 = i % 48;
                cp_async16(Ks + rr * LK + c4 * 4,
                           kbase + (size_t)(kn0 + rr) * QK_D + c4 * 4);
            }
            cp_commit();
        }

        // ---- O += P @ V ----
        #pragma unroll
        for (int kc = 0; kc < 8; kc++) {
            uint32_t a[4];
            LDMX4(a[0], a[1], a[2], a[3],
                  s2u(Ps + (qw + rselA) * LP + kc*8 + cselA));
            #pragma unroll
            for (int jp = 0; jp < 8; jp++) {
                uint32_t b0[2], b1[2];
                LDMX4(b0[0], b0[1], b1[0], b1[1],
                      s2u(Vts + (jp*16 + rselB) * LVT + kc*8 + cselB));
                MMA_TF32(oacc[2*jp],   a, b0);
                MMA_TF32(oacc[2*jp+1], a, b1);
            }
        }
        __syncthreads();       // all threads done reading Vts/Ps

        // issue V_{jt+1} — lands during S_{jt+1}
        if (jt + 1 < niter) {
            const int kn0 = (jt + 1) * 64;
            for (int i = tid; i < 128 * 16; i += 256) {
                int rr = i >> 4, c4 = i & 15;
                cp_async16(Vts + rr * LVT + c4 * 4,
                           vtbase + (size_t)rr * TT + kn0 + c4 * 4);
            }
            cp_commit();
        }
    }

    const float inv0 = 1.0f / l0;
    const float inv1 = 1.0f / l1;
    const int gr0 = qrow0 + qw + r;
    float* ob = out + ((size_t)b * TT + gr0) * (NH * V_D) + h * V_D;
    #pragma unroll
    for (int j = 0; j < 16; j++) {
        int c = 8 * j + 2 * t;
        *(float2*)(ob + c) =
            make_float2(roundtf(oacc[j][0] * inv0), roundtf(oacc[j][1] * inv0));
        *(float2*)(ob + (size_t)8 * (NH * V_D) + c) =
            make_float2(roundtf(oacc[j][2] * inv1), roundtf(oacc[j][3] * inv1));
    }
}

// ------------------------- launch -------------------------------------------
extern "C" void kernel_launch(void* const* d_in, const int* in_sizes, int n_in,
                              void* d_out, int out_size)
{
    const float* x         = (const float*)d_in[0];
    const float* W_kv_down = (const float*)d_in[1];
    const float* W_k_nope  = (const float*)d_in[2];
    const float* W_k_rope  = (const float*)d_in[3];
    const float* W_v       = (const float*)d_in[4];
    const float* W_q_down  = (const float*)d_in[5];
    const float* W_q_nope  = (const float*)d_in[6];
    const float* W_q_rope  = (const float*)d_in[7];
    const float* W_o       = (const float*)d_in[8];
    float* out = (float*)d_out;

    float *w_down, *w_kv, *w_q, *w_o, *x_r, *cdown, *kvup, *qup;
    float *qcat, *kcat, *vt, *attn, *rc, *rs;
    cudaGetSymbolAddress((void**)&w_down, g_w_down);
    cudaGetSymbolAddress((void**)&w_kv,   g_w_kv);
    cudaGetSymbolAddress((void**)&w_q,    g_w_q);
    cudaGetSymbolAddress((void**)&w_o,    g_w_o);
    cudaGetSymbolAddress((void**)&x_r,    g_x_r);
    cudaGetSymbolAddress((void**)&cdown,  g_cdown);
    cudaGetSymbolAddress((void**)&kvup,   g_kvup);
    cudaGetSymbolAddress((void**)&qup,    g_qup);
    cudaGetSymbolAddress((void**)&qcat,   g_qcat);
    cudaGetSymbolAddress((void**)&kcat,   g_kcat);
    cudaGetSymbolAddress((void**)&vt,     g_vt);
    cudaGetSymbolAddress((void**)&attn,   g_attn);
    cudaGetSymbolAddress((void**)&rc,     g_ropec);
    cudaGetSymbolAddress((void**)&rs,     g_ropes);

    cudaFuncSetAttribute(gemm_tf32, cudaFuncAttributeMaxDynamicSharedMemorySize,
                         (int)G3_SMEM);
    cudaFuncSetAttribute(flash_attn_mma, cudaFuncAttributeMaxDynamicSharedMemorySize,
                         (int)ATTN_SMEM);

    // ---- merged weight transpose+round (single launch) ----
    {
        TJobs jobs;
        const float* srcs[8] = {W_kv_down, W_q_down, W_k_nope, W_k_rope,
                                W_v, W_q_nope, W_q_rope, W_o};
        float* dsts[8] = {w_down, w_down, w_kv, w_kv, w_kv, w_q, w_q, w_o};
        int Rs[8]    = {DIM, DIM, KV_RANK, KV_RANK, KV_RANK, Q_RANK, Q_RANK, NH*V_D};
        int Cs[8]    = {KV_RANK, Q_RANK, NKV*NOPE_D, NKV*ROPE_D, NKV*V_D,
                        NH*NOPE_D, NH*ROPE_D, DIM};
        int noffs[8] = {0, KV_RANK, 0, NKV*NOPE_D, VOFF, 0, NH*NOPE_D, 0};
        int cum = 0;
        for (int k = 0; k < 8; k++) {
            jobs.src[k] = srcs[k]; jobs.dst[k] = dsts[k];
            jobs.R[k] = Rs[k]; jobs.C[k] = Cs[k]; jobs.noff[k] = noffs[k];
            jobs.start[k] = cum;
            cum += (Rs[k] / 32) * (Cs[k] / 32);
        }
        jobs.njobs = 8;
        trans_round_multi<<<cum, dim3(32, 8)>>>(jobs);
    }
    copy_round4<<<592, 256>>>((float4*)x_r, (const float4*)x, MROWS * DIM / 4);
    rope_table<<<(TT * ROPE_D + 255) / 256, 256>>>(rc, rs);

    // ---- fused down projection: [kv_c | q_c] ----
    gemm_tf32<<<dim3(N_DOWN/128, MROWS/128), 256, G3_SMEM>>>(
        x_r, DIM, w_down, cdown, N_DOWN, DIM, 1);

    // ---- fused up projections ----
    gemm_tf32<<<dim3(N_KVUP/128, MROWS/128), 256, G3_SMEM>>>(
        cdown, N_DOWN, w_kv, kvup, N_KVUP, KV_RANK, 0);
    gemm_tf32<<<dim3(N_QUP/128, MROWS/128), 256, G3_SMEM>>>(
        cdown + KV_RANK, N_DOWN, w_q, qup, N_QUP, Q_RANK, 0);

    // ---- RoPE + layout assembly + V transpose ----
    {
        size_t nq = (size_t)BB * NH * TT * QK_D;
        assemble_q<<<(unsigned)((nq + 255) / 256), 256>>>(
            qup, N_QUP, qup + NH*NOPE_D, N_QUP, rc, rs, qcat);
        size_t nk = (size_t)BB * NKV * TT * QK_D;
        assemble_k<<<(unsigned)((nk + 255) / 256), 256>>>(
            kvup, N_KVUP, kvup + NKV*NOPE_D, N_KVUP, rc, rs, kcat);
        trans_v<<<dim3(512/32, MROWS/32), dim3(32, 8)>>>(vt, kvup);
    }

    // ---- attention (1D grid, largest tiles first) ----
    flash_attn_mma<<<(TT/128) * BB * NH, 256, ATTN_SMEM>>>(qcat, kcat, vt, attn);

    // ---- output projection ----
    gemm_tf32<<<dim3(DIM/128, MROWS/128), 256, G3_SMEM>>>(
        attn, NH*V_D, w_o, out, DIM, NH*V_D, 0);
}